// round 6
// baseline (speedup 1.0000x reference)
#include <cuda_runtime.h>
#include <cuda_bf16.h>
#include <mma.h>
#include <cstddef>
#include <cstdint>

using namespace nvcuda;

#define BB    32
#define TKK   1024
#define HH    512
#define EE    256
#define VOCAB 50257
#define M_ENC (BB * TKK)   // 32768

#define FE_BLOCKS 256
#define FE_THREADS 256
#define FE_NT (FE_BLOCKS * FE_THREADS)   // 65536 threads, 2048 warps

// ---------------- scratch (__device__ globals) ------------------------------
__device__ float g_xinT[(HH + EE) * BB];
__device__ float g_hT[HH * BB];
__device__ float g_xT[EE * BB];
__device__ float g_giT[3 * HH * BB];
__device__ float g_ghT[3 * HH * BB];
__device__ float g_hnewT[HH * BB];
__device__ float g_dec[BB * HH];
__device__ float g_scores[BB * TKK];
__device__ float g_cpart[BB * 16 * HH];
__device__ float g_concatT[2 * HH * BB];
__device__ float g_out1[BB * HH];
__device__ float g_logits[(size_t)BB * VOCAB];
__device__ __nv_bfloat16 g_whb[HH * HH];      // bf16 Wh, [n][k]

__device__ unsigned g_barcnt = 0;
__device__ unsigned g_barsense = 0;

__device__ __forceinline__ float sigmoidf_(float x) { return 1.f / (1.f + __expf(-x)); }
__device__ __forceinline__ float tanh_fast(float x) {
    float r; asm("tanh.approx.f32 %0, %1;" : "=f"(r) : "f"(x)); return r;
}
__device__ __forceinline__ void cp16(uint32_t dst, const void* src) {
    asm volatile("cp.async.cg.shared.global [%0], [%1], 16;" :: "r"(dst), "l"(src));
}
__device__ __forceinline__ void cp_commit() { asm volatile("cp.async.commit_group;"); }
template<int N> __device__ __forceinline__ void cp_wait() {
    asm volatile("cp.async.wait_group %0;" :: "n"(N));
}

// ---------------- grid-wide barrier (sense reversing, self-resetting) -------
__device__ __forceinline__ void grid_bar(unsigned* sense) {
    __syncthreads();
    if (threadIdx.x == 0) {
        __threadfence();
        unsigned target = *sense ^ 1u;
        if (atomicAdd(&g_barcnt, 1u) == FE_BLOCKS - 1) {
            atomicExch(&g_barcnt, 0u);
            __threadfence();
            atomicExch(&g_barsense, target);
        } else {
            while (atomicAdd(&g_barsense, 0u) != target) {}
        }
        __threadfence();
        *sense = target;
    }
    __syncthreads();
}

// y[n,b] partial dot: W row (uniform broadcast) x AT [K][32] column b
__device__ __forceinline__ float dotk(const float4* __restrict__ w4,
                                      const float* __restrict__ a, int iters) {
    float a0 = 0.f, a1 = 0.f, a2 = 0.f, a3 = 0.f;
#pragma unroll 16
    for (int i = 0; i < iters; i++) {
        float4 w = w4[i];
        const float* ak = a + (i << 7);
        a0 += w.x * ak[0];
        a1 += w.y * ak[32];
        a2 += w.z * ak[64];
        a3 += w.w * ak[96];
    }
    return (a0 + a1) + (a2 + a3);
}

// ---------------- persistent front-end kernel -------------------------------
// S0: bias-init + build transposes + convert Wh->bf16
// S1: x = [c|emb] @ xc_w^T      S2: gi, gh      S3: GRU      S4: dec
__global__ __launch_bounds__(FE_THREADS) void k_frontend(
    const int* __restrict__ yt, const float* __restrict__ c_t_1,
    const float* __restrict__ s_t_1, const float* __restrict__ emb,
    const float* __restrict__ xc_w, const float* __restrict__ xc_b,
    const float* __restrict__ w_ih, const float* __restrict__ b_ih,
    const float* __restrict__ w_hh, const float* __restrict__ b_hh,
    const float* __restrict__ dp_w, const float* __restrict__ dp_b,
    const float* __restrict__ out1_b, const float* __restrict__ Wh,
    float* __restrict__ out_st)
{
    int tid = threadIdx.x;
    int gt = blockIdx.x * FE_THREADS + tid;
    int gw = gt >> 5, lane = gt & 31;
    unsigned sense = 0;
    if (tid == 0) sense = atomicAdd(&g_barsense, 0u);

    // ---- S0 ----
    for (int idx = gt; idx < 4352 * 32; idx += FE_NT) {
        int n = idx >> 5, b = idx & 31;
        if (n < EE)     { g_xT[n * 32 + b] = xc_b[n];  continue; }  n -= EE;
        if (n < 3 * HH) { g_giT[n * 32 + b] = b_ih[n]; continue; }  n -= 3 * HH;
        if (n < 3 * HH) { g_ghT[n * 32 + b] = b_hh[n]; continue; }  n -= 3 * HH;
        if (n < HH)     { g_dec[b * HH + n] = dp_b[n]; continue; }  n -= HH;
        g_out1[b * HH + n] = out1_b[n];
    }
    for (int idx = gt; idx < (HH + EE) * BB; idx += FE_NT) {
        int k = idx >> 5, b = idx & 31;
        g_xinT[idx] = (k < HH) ? c_t_1[b * HH + k]
                               : emb[(size_t)yt[b] * EE + (k - HH)];
    }
    for (int idx = gt; idx < HH * BB; idx += FE_NT) {
        int k = idx >> 5, b = idx & 31;
        g_hT[idx] = s_t_1[b * HH + k];
    }
    for (int i = gt; i < HH * HH / 2; i += FE_NT) {
        float2 v = *(const float2*)(Wh + (size_t)i * 2);
        *(__nv_bfloat162*)(g_whb + (size_t)i * 2) = __floats2bfloat162_rn(v.x, v.y);
    }
    grid_bar(&sense);

    // ---- S1: x (N=256, K=768, split 8 -> 2048 units, 24 iters) ----
    {
        int n = gw >> 3, sp = gw & 7;
        int k0 = sp * 96;
        float r = dotk((const float4*)(xc_w + (size_t)n * (HH + EE) + k0),
                       g_xinT + k0 * 32 + lane, 24);
        atomicAdd(&g_xT[n * 32 + lane], r);
    }
    grid_bar(&sense);

    // ---- S2: gi (N=1536,K=256,split2) + gh (N=1536,K=512,split4) ----
    for (int u = gw; u < 9216; u += 2048) {
        if (u < 3072) {
            int n = u >> 1, sp = u & 1, k0 = sp * 128;
            float r = dotk((const float4*)(w_ih + (size_t)n * EE + k0),
                           g_xT + k0 * 32 + lane, 32);
            atomicAdd(&g_giT[n * 32 + lane], r);
        } else {
            int v = u - 3072;
            int n = v >> 2, sp = v & 3, k0 = sp * 128;
            float r = dotk((const float4*)(w_hh + (size_t)n * HH + k0),
                           g_hT + k0 * 32 + lane, 32);
            atomicAdd(&g_ghT[n * 32 + lane], r);
        }
    }
    grid_bar(&sense);

    // ---- S3: GRU ----
    if (gt < HH * BB) {
        int j = gt >> 5, b = gt & 31;
        float ir = g_giT[j * BB + b],             hr = g_ghT[j * BB + b];
        float iz = g_giT[(HH + j) * BB + b],      hz = g_ghT[(HH + j) * BB + b];
        float in_ = g_giT[(2 * HH + j) * BB + b], hn = g_ghT[(2 * HH + j) * BB + b];
        float r = sigmoidf_(ir + hr);
        float z = sigmoidf_(iz + hz);
        float nn = tanhf(in_ + r * hn);
        float h = g_hT[j * BB + b];
        float hv = (1.f - z) * nn + z * h;
        g_hnewT[j * BB + b] = hv;
        g_concatT[j * BB + b] = hv;
        out_st[b * HH + j] = hv;
    }
    grid_bar(&sense);

    // ---- S4: dec (N=512, K=512, split 4 -> 2048 units, 32 iters) ----
    {
        int n = gw >> 2, sp = gw & 3, k0 = sp * 128;
        float r = dotk((const float4*)(dp_w + (size_t)n * HH + k0),
                       g_hnewT + k0 * 32 + lane, 32);
        atomicAdd(&g_dec[lane * HH + n], r);
    }
}

// ---------------- split-K small GEMM (used for out1 only) -------------------
__global__ __launch_bounds__(256) void k_bsplit(float* __restrict__ yT,
                                                float* __restrict__ yR,
                                                const float* __restrict__ AT,
                                                const float* __restrict__ W,
                                                int N, int K) {
    int warp = threadIdx.x >> 5, lane = threadIdx.x & 31;
    int n = blockIdx.x * 8 + warp;
    int kchunk = K / gridDim.y;
    int k0 = blockIdx.y * kchunk;
    float r = dotk((const float4*)(W + (size_t)n * K + k0),
                   AT + k0 * 32 + lane, kchunk >> 2);
    if (yT) atomicAdd(&yT[n * 32 + lane], r);
    if (yR) atomicAdd(&yR[(size_t)lane * N + n], r);
}

// ---------------- fused: scores = v . tanh(enc@Wh^T + dec) ------------------
// block 512 thr, tile M=64 x N=512, K pipelined in chunks of 32 (cp.async).
#define FA_SMEM (4096 + 133120)
__global__ __launch_bounds__(512) void k_fused_attn(const float* __restrict__ enc,
                                                    const float* __restrict__ vw) {
    extern __shared__ char smraw[];
    float* sdec = (float*)smraw;                         // [512]
    float* sv   = sdec + 512;                            // [512]
    __nv_bfloat16* As = (__nv_bfloat16*)(smraw + 4096);  // [2][64][40]
    __nv_bfloat16* Bs = (__nv_bfloat16*)(smraw + 14336); // [3][512][40]
    float* stage = (float*)(smraw + 4096);               // [64][520] (epilogue)

    int tid = threadIdx.x, warp = tid >> 5, lane = tid & 31;
    int bt = blockIdx.x;
    int b  = bt >> 4;
    size_t m0 = (size_t)bt * 64;

    sdec[tid] = g_dec[b * HH + tid];
    sv[tid]   = vw[tid];

    int wm = warp >> 3, wn = warp & 7;
    wmma::fragment<wmma::accumulator, 16, 16, 16, float> acc[2][4];
#pragma unroll
    for (int i = 0; i < 2; i++)
#pragma unroll
        for (int j = 0; j < 4; j++) wmma::fill_fragment(acc[i][j], 0.f);

    uint32_t bs_base = (uint32_t)__cvta_generic_to_shared(Bs);
    int arow = tid >> 3, aq = tid & 7;

    {
        uint32_t dst = bs_base + tid * 80;
        const char* src = (const char*)(g_whb + tid * HH);
#pragma unroll
        for (int j = 0; j < 4; j++) cp16(dst + j * 16, src + j * 16);
        cp_commit();
    }
    float4 areg = *(const float4*)(enc + (m0 + arow) * HH + aq * 4);

    const int NIT = HH / 32;   // 16
    for (int it = 0; it < NIT; it++) {
        int cur2 = it & 1, cur3 = it - (it / 3) * 3;
        if (it < NIT - 1) {
            int n3 = (it + 1) - ((it + 1) / 3) * 3;
            uint32_t dst = bs_base + n3 * 40960 + tid * 80;
            const char* src = (const char*)(g_whb + tid * HH + (it + 1) * 32);
#pragma unroll
            for (int j = 0; j < 4; j++) cp16(dst + j * 16, src + j * 16);
            cp_commit();
        }
        __nv_bfloat16* ad = As + cur2 * (64 * 40) + arow * 40 + aq * 4;
        *(__nv_bfloat162*)ad       = __floats2bfloat162_rn(areg.x, areg.y);
        *(__nv_bfloat162*)(ad + 2) = __floats2bfloat162_rn(areg.z, areg.w);
        if (it < NIT - 1)
            areg = *(const float4*)(enc + (m0 + arow) * HH + (it + 1) * 32 + aq * 4);
        if (it < NIT - 1) cp_wait<1>(); else cp_wait<0>();
        __syncthreads();
        const __nv_bfloat16* ab = As + cur2 * (64 * 40);
        const __nv_bfloat16* bb = Bs + cur3 * (512 * 40);
#pragma unroll
        for (int kk = 0; kk < 32; kk += 16) {
            wmma::fragment<wmma::matrix_a, 16, 16, 16, __nv_bfloat16, wmma::row_major> af[2];
#pragma unroll
            for (int i = 0; i < 2; i++)
                wmma::load_matrix_sync(af[i], ab + (wm * 32 + i * 16) * 40 + kk, 40);
#pragma unroll
            for (int j = 0; j < 4; j++) {
                wmma::fragment<wmma::matrix_b, 16, 16, 16, __nv_bfloat16, wmma::col_major> bf;
                wmma::load_matrix_sync(bf, bb + (wn * 64 + j * 16) * 40 + kk, 40);
                wmma::mma_sync(acc[0][j], af[0], bf, acc[0][j]);
                wmma::mma_sync(acc[1][j], af[1], bf, acc[1][j]);
            }
        }
        __syncthreads();
    }
#pragma unroll
    for (int i = 0; i < 2; i++)
#pragma unroll
        for (int j = 0; j < 4; j++)
            wmma::store_matrix_sync(stage + (wm * 32 + i * 16) * 520 + wn * 64 + j * 16,
                                    acc[i][j], 520, wmma::mem_row_major);
    __syncthreads();
#pragma unroll
    for (int rr = 0; rr < 4; rr++) {
        int r = warp * 4 + rr;
        const float* sr = stage + r * 520;
        float a = 0.f;
#pragma unroll
        for (int itn = 0; itn < 16; itn++) {
            int n = lane + itn * 32;
            a += sv[n] * tanh_fast(sr[n] + sdec[n]);
        }
#pragma unroll
        for (int o = 16; o; o >>= 1) a += __shfl_down_sync(0xffffffffu, a, o);
        if (lane == 0) g_scores[bt * 64 + r] = a;
    }
}

// ---------------- softmax over TK per b -------------------------------------
__global__ void k_attn(float* __restrict__ out_attn) {
    __shared__ float red[32];
    int b = blockIdx.x, t = threadIdx.x;   // 1024 threads
    float s = g_scores[b * TKK + t];
    float m = s;
#pragma unroll
    for (int o = 16; o; o >>= 1) m = fmaxf(m, __shfl_xor_sync(0xffffffffu, m, o));
    if ((t & 31) == 0) red[t >> 5] = m;
    __syncthreads();
    if (t < 32) {
        float v = red[t];
#pragma unroll
        for (int o = 16; o; o >>= 1) v = fmaxf(v, __shfl_xor_sync(0xffffffffu, v, o));
        if (t == 0) red[0] = v;
    }
    __syncthreads();
    float mx = red[0];
    __syncthreads();
    float e = __expf(s - mx);
    float sm = e;
#pragma unroll
    for (int o = 16; o; o >>= 1) sm += __shfl_xor_sync(0xffffffffu, sm, o);
    if ((t & 31) == 0) red[t >> 5] = sm;
    __syncthreads();
    if (t < 32) {
        float v = red[t];
#pragma unroll
        for (int o = 16; o; o >>= 1) v += __shfl_xor_sync(0xffffffffu, v, o);
        if (t == 0) red[0] = v;
    }
    __syncthreads();
    out_attn[b * TKK + t] = e * (1.f / red[0]);
}

// ---------------- c_t partials ----------------------------------------------
__global__ void k_ct_part(const float* __restrict__ enc, const float* __restrict__ attn) {
    __shared__ float sa[64];
    int c = blockIdx.x, b = blockIdx.y, h = threadIdx.x;   // 512 threads
    if (h < 64) sa[h] = attn[b * TKK + c * 64 + h];
    __syncthreads();
    const float* e = enc + ((size_t)b * TKK + c * 64) * HH + h;
    float acc = 0.f;
#pragma unroll 8
    for (int t = 0; t < 64; t++) acc += sa[t] * e[(size_t)t * HH];
    g_cpart[((size_t)b * 16 + c) * HH + h] = acc;
}

__global__ void k_ct_fin(float* __restrict__ out_ct) {
    int b = blockIdx.x, h = threadIdx.x;   // 512
    float acc = 0.f;
#pragma unroll
    for (int c = 0; c < 16; c++) acc += g_cpart[((size_t)b * 16 + c) * HH + h];
    out_ct[b * HH + h] = acc;
    g_concatT[(HH + h) * BB + b] = acc;
}

// ---------------- logits via wmma, double buffered --------------------------
#define LG_SMEM (33280 + 20480)
__global__ __launch_bounds__(256) void k_logits_mma(const float* __restrict__ W,
                                                    const float* __restrict__ bias) {
    extern __shared__ char smraw[];
    __nv_bfloat16* As2 = (__nv_bfloat16*)smraw;                // [32][520]
    __nv_bfloat16* Ws  = (__nv_bfloat16*)(smraw + 33280);      // [2][128][40]
    float* stage = (float*)(smraw + 33280);                    // [32][136]

    int tid = threadIdx.x, warp = tid >> 5;
    int n0 = blockIdx.x * 128;
    for (int idx = tid; idx < BB * HH; idx += 256) {
        int r = idx >> 9, k = idx & 511;
        As2[r * 520 + k] = __float2bfloat16(g_out1[idx]);
    }

    wmma::fragment<wmma::accumulator, 16, 16, 16, float> acc[2];
    wmma::fill_fragment(acc[0], 0.f);
    wmma::fill_fragment(acc[1], 0.f);

    int lrow = tid >> 3, lq = tid & 7;
    float4 wreg[4];
#pragma unroll
    for (int p = 0; p < 4; p++) {
        int n = n0 + p * 32 + lrow;
        wreg[p] = (n < VOCAB) ? *(const float4*)(W + (size_t)n * HH + lq * 4)
                              : make_float4(0.f, 0.f, 0.f, 0.f);
    }
    for (int it = 0; it < 16; it++) {
        int cur = it & 1;
        __nv_bfloat16* wd = Ws + cur * (128 * 40);
#pragma unroll
        for (int p = 0; p < 4; p++) {
            __nv_bfloat16* d = wd + (p * 32 + lrow) * 40 + lq * 4;
            *(__nv_bfloat162*)d       = __floats2bfloat162_rn(wreg[p].x, wreg[p].y);
            *(__nv_bfloat162*)(d + 2) = __floats2bfloat162_rn(wreg[p].z, wreg[p].w);
        }
        if (it < 15) {
#pragma unroll
            for (int p = 0; p < 4; p++) {
                int n = n0 + p * 32 + lrow;
                wreg[p] = (n < VOCAB)
                    ? *(const float4*)(W + (size_t)n * HH + (it + 1) * 32 + lq * 4)
                    : make_float4(0.f, 0.f, 0.f, 0.f);
            }
        }
        __syncthreads();
#pragma unroll
        for (int kk = 0; kk < 32; kk += 16) {
            wmma::fragment<wmma::matrix_b, 16, 16, 16, __nv_bfloat16, wmma::col_major> bf;
            wmma::load_matrix_sync(bf, wd + (warp * 16) * 40 + kk, 40);
#pragma unroll
            for (int i = 0; i < 2; i++) {
                wmma::fragment<wmma::matrix_a, 16, 16, 16, __nv_bfloat16, wmma::row_major> af;
                wmma::load_matrix_sync(af, As2 + (i * 16) * 520 + it * 32 + kk, 520);
                wmma::mma_sync(acc[i], af, bf, acc[i]);
            }
        }
        __syncthreads();
    }
#pragma unroll
    for (int i = 0; i < 2; i++)
        wmma::store_matrix_sync(stage + (i * 16) * 136 + warp * 16, acc[i], 136,
                                wmma::mem_row_major);
    __syncthreads();
    for (int idx = tid; idx < 32 * 128; idx += 256) {
        int r = idx >> 7, c = idx & 127;
        int n = n0 + c;
        if (n < VOCAB)
            g_logits[(size_t)r * VOCAB + n] = stage[r * 136 + c] + bias[n];
    }
}

// ---------------- softmax over V per b --------------------------------------
__global__ void k_softmaxV(float* __restrict__ out_fd) {
    __shared__ float red[32];
    int b = blockIdx.x, tid = threadIdx.x;     // 512 threads
    const float* lg = g_logits + (size_t)b * VOCAB;
    float* dst = out_fd + (size_t)b * VOCAB;

    float m = -1e30f;
    for (int n = tid; n < VOCAB; n += 512) m = fmaxf(m, lg[n]);
#pragma unroll
    for (int o = 16; o; o >>= 1) m = fmaxf(m, __shfl_xor_sync(0xffffffffu, m, o));
    if ((tid & 31) == 0) red[tid >> 5] = m;
    __syncthreads();
    if (tid < 32) {
        float v = (tid < 16) ? red[tid] : -1e30f;
#pragma unroll
        for (int o = 16; o; o >>= 1) v = fmaxf(v, __shfl_xor_sync(0xffffffffu, v, o));
        if (tid == 0) red[0] = v;
    }
    __syncthreads();
    float mx = red[0];
    __syncthreads();
    float s = 0.f;
    for (int n = tid; n < VOCAB; n += 512) {
        float e = __expf(lg[n] - mx);
        dst[n] = e;
        s += e;
    }
#pragma unroll
    for (int o = 16; o; o >>= 1) s += __shfl_xor_sync(0xffffffffu, s, o);
    if ((tid & 31) == 0) red[tid >> 5] = s;
    __syncthreads();
    if (tid < 32) {
        float v = (tid < 16) ? red[tid] : 0.f;
#pragma unroll
        for (int o = 16; o; o >>= 1) v += __shfl_xor_sync(0xffffffffu, v, o);
        if (tid == 0) red[0] = v;
    }
    __syncthreads();
    float inv = 1.f / red[0];
    for (int n = tid; n < VOCAB; n += 512) dst[n] *= inv;
}

// ---------------- launcher ---------------------------------------------------
extern "C" void kernel_launch(void* const* d_in, const int* in_sizes, int n_in,
                              void* d_out, int out_size) {
    const int*   y      = (const int*)d_in[0];
    const float* s_t_1  = (const float*)d_in[2];
    const float* enc    = (const float*)d_in[3];
    const float* c_t_1  = (const float*)d_in[4];
    const float* cov    = (const float*)d_in[5];
    const float* emb    = (const float*)d_in[7];
    const float* xc_w   = (const float*)d_in[8];
    const float* xc_b   = (const float*)d_in[9];
    const float* Wh_w   = (const float*)d_in[10];
    const float* w_ih   = (const float*)d_in[11];
    const float* w_hh   = (const float*)d_in[12];
    const float* b_ih   = (const float*)d_in[13];
    const float* b_hh   = (const float*)d_in[14];
    const float* dp_w   = (const float*)d_in[15];
    const float* dp_b   = (const float*)d_in[16];
    const float* v_w    = (const float*)d_in[17];
    const float* out1_w = (const float*)d_in[18];
    const float* out1_b = (const float*)d_in[19];
    const float* out2_w = (const float*)d_in[20];
    const float* out2_b = (const float*)d_in[21];

    float* out      = (float*)d_out;
    float* out_fd   = out;
    float* out_st   = out_fd + (size_t)BB * VOCAB;
    float* out_ct   = out_st + BB * HH;
    float* out_attn = out_ct + BB * HH;
    float* out_cov  = out_attn + BB * TKK;

    float *p_concatT, *p_out1;
    cudaGetSymbolAddress((void**)&p_concatT, g_concatT);
    cudaGetSymbolAddress((void**)&p_out1,    g_out1);

    cudaFuncSetAttribute(k_fused_attn, cudaFuncAttributeMaxDynamicSharedMemorySize, FA_SMEM);
    cudaFuncSetAttribute(k_logits_mma, cudaFuncAttributeMaxDynamicSharedMemorySize, LG_SMEM);

    // whole front-end in one persistent kernel
    k_frontend<<<FE_BLOCKS, FE_THREADS>>>(y, c_t_1, s_t_1, emb,
                                          xc_w, xc_b, w_ih, b_ih, w_hh, b_hh,
                                          dp_w, dp_b, out1_b, Wh_w, out_st);
    // fused attention scores
    k_fused_attn<<<M_ENC / 64, 512, FA_SMEM>>>(enc, v_w);
    k_attn<<<BB, 1024>>>(out_attn);
    k_ct_part<<<dim3(16, BB), 512>>>(enc, out_attn);
    k_ct_fin<<<BB, 512>>>(out_ct);
    // out1 = concat @ out1_w^T (N=512, K=1024, splits=8)
    k_bsplit<<<dim3(HH / 8, 8), 256>>>(nullptr, p_out1, p_concatT, out1_w, HH, 2 * HH);
    k_logits_mma<<<(VOCAB + 127) / 128, 256, LG_SMEM>>>(out2_w, out2_b);
    k_softmaxV<<<BB, 512>>>(out_fd);
    cudaMemcpyAsync(out_cov, cov, (size_t)BB * TKK * sizeof(float),
                    cudaMemcpyDeviceToDevice, 0);
}

// round 7
// speedup vs baseline: 1.0066x; 1.0066x over previous
#include <cuda_runtime.h>
#include <cuda_bf16.h>
#include <mma.h>
#include <cstddef>
#include <cstdint>

using namespace nvcuda;

#define BB    32
#define TKK   1024
#define HH    512
#define EE    256
#define VOCAB 50257
#define M_ENC (BB * TKK)   // 32768

#define FE_BLOCKS 256
#define FE_THREADS 256
#define FE_NT (FE_BLOCKS * FE_THREADS)   // 65536 threads, 2048 warps

// ---------------- scratch (__device__ globals) ------------------------------
__device__ float g_xinT[(HH + EE) * BB];
__device__ float g_hT[HH * BB];
__device__ float g_xT[EE * BB];
__device__ float g_giT[3 * HH * BB];
__device__ float g_ghT[3 * HH * BB];
__device__ float g_hnewT[HH * BB];
__device__ float g_dec[BB * HH];
__device__ float g_scores[BB * TKK];
__device__ float g_cpart[BB * 16 * HH];
__device__ float g_concatT[2 * HH * BB];
__device__ float g_out1[BB * HH];
__device__ float g_logits[(size_t)BB * VOCAB];
__device__ __nv_bfloat16 g_whb[HH * HH];      // bf16 Wh, [n][k]

__device__ unsigned g_barcnt = 0;
__device__ unsigned g_barsense = 0;

__device__ __forceinline__ float sigmoidf_(float x) { return 1.f / (1.f + __expf(-x)); }
__device__ __forceinline__ float tanh_fast(float x) {
    float r; asm("tanh.approx.f32 %0, %1;" : "=f"(r) : "f"(x)); return r;
}
__device__ __forceinline__ void cp16(uint32_t dst, const void* src) {
    asm volatile("cp.async.cg.shared.global [%0], [%1], 16;" :: "r"(dst), "l"(src));
}
__device__ __forceinline__ void cp_commit() { asm volatile("cp.async.commit_group;"); }
template<int N> __device__ __forceinline__ void cp_wait() {
    asm volatile("cp.async.wait_group %0;" :: "n"(N));
}

// ---------------- grid-wide barrier (sense reversing, self-resetting) -------
__device__ __forceinline__ void grid_bar(unsigned* sense) {
    __syncthreads();
    if (threadIdx.x == 0) {
        __threadfence();
        unsigned target = *sense ^ 1u;
        if (atomicAdd(&g_barcnt, 1u) == FE_BLOCKS - 1) {
            atomicExch(&g_barcnt, 0u);
            __threadfence();
            atomicExch(&g_barsense, target);
        } else {
            while (atomicAdd(&g_barsense, 0u) != target) {}
        }
        __threadfence();
        *sense = target;
    }
    __syncthreads();
}

// y[n,b] partial dot: W row (uniform broadcast) x AT [K][32] column b
__device__ __forceinline__ float dotk(const float4* __restrict__ w4,
                                      const float* __restrict__ a, int iters) {
    float a0 = 0.f, a1 = 0.f, a2 = 0.f, a3 = 0.f;
#pragma unroll 16
    for (int i = 0; i < iters; i++) {
        float4 w = w4[i];
        const float* ak = a + (i << 7);
        a0 += w.x * ak[0];
        a1 += w.y * ak[32];
        a2 += w.z * ak[64];
        a3 += w.w * ak[96];
    }
    return (a0 + a1) + (a2 + a3);
}

// ---------------- persistent front-end kernel -------------------------------
// S0: bias-init + build transposes + convert Wh->bf16
// S1: x = [c|emb] @ xc_w^T      S2: gi, gh      S3: GRU      S4: dec
__global__ __launch_bounds__(FE_THREADS) void k_frontend(
    const int* __restrict__ yt, const float* __restrict__ c_t_1,
    const float* __restrict__ s_t_1, const float* __restrict__ emb,
    const float* __restrict__ xc_w, const float* __restrict__ xc_b,
    const float* __restrict__ w_ih, const float* __restrict__ b_ih,
    const float* __restrict__ w_hh, const float* __restrict__ b_hh,
    const float* __restrict__ dp_w, const float* __restrict__ dp_b,
    const float* __restrict__ out1_b, const float* __restrict__ Wh,
    float* __restrict__ out_st)
{
    int tid = threadIdx.x;
    int gt = blockIdx.x * FE_THREADS + tid;
    int gw = gt >> 5, lane = gt & 31;
    unsigned sense = 0;
    if (tid == 0) sense = atomicAdd(&g_barsense, 0u);

    // ---- S0 ----
    for (int idx = gt; idx < 4352 * 32; idx += FE_NT) {
        int n = idx >> 5, b = idx & 31;
        if (n < EE)     { g_xT[n * 32 + b] = xc_b[n];  continue; }  n -= EE;
        if (n < 3 * HH) { g_giT[n * 32 + b] = b_ih[n]; continue; }  n -= 3 * HH;
        if (n < 3 * HH) { g_ghT[n * 32 + b] = b_hh[n]; continue; }  n -= 3 * HH;
        if (n < HH)     { g_dec[b * HH + n] = dp_b[n]; continue; }  n -= HH;
        g_out1[b * HH + n] = out1_b[n];
    }
    for (int idx = gt; idx < (HH + EE) * BB; idx += FE_NT) {
        int k = idx >> 5, b = idx & 31;
        g_xinT[idx] = (k < HH) ? c_t_1[b * HH + k]
                               : emb[(size_t)yt[b] * EE + (k - HH)];
    }
    for (int idx = gt; idx < HH * BB; idx += FE_NT) {
        int k = idx >> 5, b = idx & 31;
        g_hT[idx] = s_t_1[b * HH + k];
    }
    for (int i = gt; i < HH * HH / 2; i += FE_NT) {
        float2 v = *(const float2*)(Wh + (size_t)i * 2);
        *(__nv_bfloat162*)(g_whb + (size_t)i * 2) = __floats2bfloat162_rn(v.x, v.y);
    }
    grid_bar(&sense);

    // ---- S1: x (N=256, K=768, split 8 -> 2048 units, 24 iters) ----
    {
        int n = gw >> 3, sp = gw & 7;
        int k0 = sp * 96;
        float r = dotk((const float4*)(xc_w + (size_t)n * (HH + EE) + k0),
                       g_xinT + k0 * 32 + lane, 24);
        atomicAdd(&g_xT[n * 32 + lane], r);
    }
    grid_bar(&sense);

    // ---- S2: gi (N=1536,K=256,split2) + gh (N=1536,K=512,split4) ----
    for (int u = gw; u < 9216; u += 2048) {
        if (u < 3072) {
            int n = u >> 1, sp = u & 1, k0 = sp * 128;
            float r = dotk((const float4*)(w_ih + (size_t)n * EE + k0),
                           g_xT + k0 * 32 + lane, 32);
            atomicAdd(&g_giT[n * 32 + lane], r);
        } else {
            int v = u - 3072;
            int n = v >> 2, sp = v & 3, k0 = sp * 128;
            float r = dotk((const float4*)(w_hh + (size_t)n * HH + k0),
                           g_hT + k0 * 32 + lane, 32);
            atomicAdd(&g_ghT[n * 32 + lane], r);
        }
    }
    grid_bar(&sense);

    // ---- S3: GRU ----
    if (gt < HH * BB) {
        int j = gt >> 5, b = gt & 31;
        float ir = g_giT[j * BB + b],             hr = g_ghT[j * BB + b];
        float iz = g_giT[(HH + j) * BB + b],      hz = g_ghT[(HH + j) * BB + b];
        float in_ = g_giT[(2 * HH + j) * BB + b], hn = g_ghT[(2 * HH + j) * BB + b];
        float r = sigmoidf_(ir + hr);
        float z = sigmoidf_(iz + hz);
        float nn = tanhf(in_ + r * hn);
        float h = g_hT[j * BB + b];
        float hv = (1.f - z) * nn + z * h;
        g_hnewT[j * BB + b] = hv;
        g_concatT[j * BB + b] = hv;
        out_st[b * HH + j] = hv;
    }
    grid_bar(&sense);

    // ---- S4: dec (N=512, K=512, split 4 -> 2048 units, 32 iters) ----
    {
        int n = gw >> 2, sp = gw & 3, k0 = sp * 128;
        float r = dotk((const float4*)(dp_w + (size_t)n * HH + k0),
                       g_hnewT + k0 * 32 + lane, 32);
        atomicAdd(&g_dec[lane * HH + n], r);
    }
}

// ---------------- split-K small GEMM (used for out1 only) -------------------
__global__ __launch_bounds__(256) void k_bsplit(float* __restrict__ yT,
                                                float* __restrict__ yR,
                                                const float* __restrict__ AT,
                                                const float* __restrict__ W,
                                                int N, int K) {
    int warp = threadIdx.x >> 5, lane = threadIdx.x & 31;
    int n = blockIdx.x * 8 + warp;
    int kchunk = K / gridDim.y;
    int k0 = blockIdx.y * kchunk;
    float r = dotk((const float4*)(W + (size_t)n * K + k0),
                   AT + k0 * 32 + lane, kchunk >> 2);
    if (yT) atomicAdd(&yT[n * 32 + lane], r);
    if (yR) atomicAdd(&yR[(size_t)lane * N + n], r);
}

// ---------------- fused: scores = v . tanh(enc@Wh^T + dec) ------------------
// block 512 thr, tile M=64 x N=512, K pipelined in chunks of 32 (cp.async).
#define FA_SMEM (4096 + 133120)
__global__ __launch_bounds__(512) void k_fused_attn(const float* __restrict__ enc,
                                                    const float* __restrict__ vw) {
    extern __shared__ char smraw[];
    float* sdec = (float*)smraw;                         // [512]
    float* sv   = sdec + 512;                            // [512]
    __nv_bfloat16* As = (__nv_bfloat16*)(smraw + 4096);  // [2][64][40]
    __nv_bfloat16* Bs = (__nv_bfloat16*)(smraw + 14336); // [3][512][40]
    float* stage = (float*)(smraw + 4096);               // [64][520] (epilogue)

    int tid = threadIdx.x, warp = tid >> 5, lane = tid & 31;
    int bt = blockIdx.x;
    int b  = bt >> 4;
    size_t m0 = (size_t)bt * 64;

    sdec[tid] = g_dec[b * HH + tid];
    sv[tid]   = vw[tid];

    int wm = warp >> 3, wn = warp & 7;
    wmma::fragment<wmma::accumulator, 16, 16, 16, float> acc[2][4];
#pragma unroll
    for (int i = 0; i < 2; i++)
#pragma unroll
        for (int j = 0; j < 4; j++) wmma::fill_fragment(acc[i][j], 0.f);

    uint32_t bs_base = (uint32_t)__cvta_generic_to_shared(Bs);
    int arow = tid >> 3, aq = tid & 7;

    {
        uint32_t dst = bs_base + tid * 80;
        const char* src = (const char*)(g_whb + tid * HH);
#pragma unroll
        for (int j = 0; j < 4; j++) cp16(dst + j * 16, src + j * 16);
        cp_commit();
    }
    float4 areg = *(const float4*)(enc + (m0 + arow) * HH + aq * 4);

    const int NIT = HH / 32;   // 16
    for (int it = 0; it < NIT; it++) {
        int cur2 = it & 1, cur3 = it - (it / 3) * 3;
        if (it < NIT - 1) {
            int n3 = (it + 1) - ((it + 1) / 3) * 3;
            uint32_t dst = bs_base + n3 * 40960 + tid * 80;
            const char* src = (const char*)(g_whb + tid * HH + (it + 1) * 32);
#pragma unroll
            for (int j = 0; j < 4; j++) cp16(dst + j * 16, src + j * 16);
            cp_commit();
        }
        __nv_bfloat16* ad = As + cur2 * (64 * 40) + arow * 40 + aq * 4;
        *(__nv_bfloat162*)ad       = __floats2bfloat162_rn(areg.x, areg.y);
        *(__nv_bfloat162*)(ad + 2) = __floats2bfloat162_rn(areg.z, areg.w);
        if (it < NIT - 1)
            areg = *(const float4*)(enc + (m0 + arow) * HH + (it + 1) * 32 + aq * 4);
        if (it < NIT - 1) cp_wait<1>(); else cp_wait<0>();
        __syncthreads();
        const __nv_bfloat16* ab = As + cur2 * (64 * 40);
        const __nv_bfloat16* bb = Bs + cur3 * (512 * 40);
#pragma unroll
        for (int kk = 0; kk < 32; kk += 16) {
            wmma::fragment<wmma::matrix_a, 16, 16, 16, __nv_bfloat16, wmma::row_major> af[2];
#pragma unroll
            for (int i = 0; i < 2; i++)
                wmma::load_matrix_sync(af[i], ab + (wm * 32 + i * 16) * 40 + kk, 40);
#pragma unroll
            for (int j = 0; j < 4; j++) {
                wmma::fragment<wmma::matrix_b, 16, 16, 16, __nv_bfloat16, wmma::col_major> bf;
                wmma::load_matrix_sync(bf, bb + (wn * 64 + j * 16) * 40 + kk, 40);
                wmma::mma_sync(acc[0][j], af[0], bf, acc[0][j]);
                wmma::mma_sync(acc[1][j], af[1], bf, acc[1][j]);
            }
        }
        __syncthreads();
    }
#pragma unroll
    for (int i = 0; i < 2; i++)
#pragma unroll
        for (int j = 0; j < 4; j++)
            wmma::store_matrix_sync(stage + (wm * 32 + i * 16) * 520 + wn * 64 + j * 16,
                                    acc[i][j], 520, wmma::mem_row_major);
    __syncthreads();
#pragma unroll
    for (int rr = 0; rr < 4; rr++) {
        int r = warp * 4 + rr;
        const float* sr = stage + r * 520;
        float a = 0.f;
#pragma unroll
        for (int itn = 0; itn < 16; itn++) {
            int n = lane + itn * 32;
            a += sv[n] * tanh_fast(sr[n] + sdec[n]);
        }
#pragma unroll
        for (int o = 16; o; o >>= 1) a += __shfl_down_sync(0xffffffffu, a, o);
        if (lane == 0) g_scores[bt * 64 + r] = a;
    }
}

// ---------------- softmax over TK per b -------------------------------------
__global__ void k_attn(float* __restrict__ out_attn) {
    __shared__ float red[32];
    int b = blockIdx.x, t = threadIdx.x;   // 1024 threads
    float s = g_scores[b * TKK + t];
    float m = s;
#pragma unroll
    for (int o = 16; o; o >>= 1) m = fmaxf(m, __shfl_xor_sync(0xffffffffu, m, o));
    if ((t & 31) == 0) red[t >> 5] = m;
    __syncthreads();
    if (t < 32) {
        float v = red[t];
#pragma unroll
        for (int o = 16; o; o >>= 1) v = fmaxf(v, __shfl_xor_sync(0xffffffffu, v, o));
        if (t == 0) red[0] = v;
    }
    __syncthreads();
    float mx = red[0];
    __syncthreads();
    float e = __expf(s - mx);
    float sm = e;
#pragma unroll
    for (int o = 16; o; o >>= 1) sm += __shfl_xor_sync(0xffffffffu, sm, o);
    if ((t & 31) == 0) red[t >> 5] = sm;
    __syncthreads();
    if (t < 32) {
        float v = red[t];
#pragma unroll
        for (int o = 16; o; o >>= 1) v += __shfl_xor_sync(0xffffffffu, v, o);
        if (t == 0) red[0] = v;
    }
    __syncthreads();
    out_attn[b * TKK + t] = e * (1.f / red[0]);
}

// ---------------- c_t partials ----------------------------------------------
__global__ void k_ct_part(const float* __restrict__ enc, const float* __restrict__ attn) {
    __shared__ float sa[64];
    int c = blockIdx.x, b = blockIdx.y, h = threadIdx.x;   // 512 threads
    if (h < 64) sa[h] = attn[b * TKK + c * 64 + h];
    __syncthreads();
    const float* e = enc + ((size_t)b * TKK + c * 64) * HH + h;
    float acc = 0.f;
#pragma unroll 8
    for (int t = 0; t < 64; t++) acc += sa[t] * e[(size_t)t * HH];
    g_cpart[((size_t)b * 16 + c) * HH + h] = acc;
}

__global__ void k_ct_fin(float* __restrict__ out_ct) {
    int b = blockIdx.x, h = threadIdx.x;   // 512
    float acc = 0.f;
#pragma unroll
    for (int c = 0; c < 16; c++) acc += g_cpart[((size_t)b * 16 + c) * HH + h];
    out_ct[b * HH + h] = acc;
    g_concatT[(HH + h) * BB + b] = acc;
}

// ---------------- logits via wmma, double buffered --------------------------
#define LG_SMEM (33280 + 20480)
__global__ __launch_bounds__(256) void k_logits_mma(const float* __restrict__ W,
                                                    const float* __restrict__ bias) {
    extern __shared__ char smraw[];
    __nv_bfloat16* As2 = (__nv_bfloat16*)smraw;                // [32][520]
    __nv_bfloat16* Ws  = (__nv_bfloat16*)(smraw + 33280);      // [2][128][40]
    float* stage = (float*)(smraw + 33280);                    // [32][136]

    int tid = threadIdx.x, warp = tid >> 5;
    int n0 = blockIdx.x * 128;
    for (int idx = tid; idx < BB * HH; idx += 256) {
        int r = idx >> 9, k = idx & 511;
        As2[r * 520 + k] = __float2bfloat16(g_out1[idx]);
    }

    wmma::fragment<wmma::accumulator, 16, 16, 16, float> acc[2];
    wmma::fill_fragment(acc[0], 0.f);
    wmma::fill_fragment(acc[1], 0.f);

    int lrow = tid >> 3, lq = tid & 7;
    float4 wreg[4];
#pragma unroll
    for (int p = 0; p < 4; p++) {
        int n = n0 + p * 32 + lrow;
        wreg[p] = (n < VOCAB) ? *(const float4*)(W + (size_t)n * HH + lq * 4)
                              : make_float4(0.f, 0.f, 0.f, 0.f);
    }
    for (int it = 0; it < 16; it++) {
        int cur = it & 1;
        __nv_bfloat16* wd = Ws + cur * (128 * 40);
#pragma unroll
        for (int p = 0; p < 4; p++) {
            __nv_bfloat16* d = wd + (p * 32 + lrow) * 40 + lq * 4;
            *(__nv_bfloat162*)d       = __floats2bfloat162_rn(wreg[p].x, wreg[p].y);
            *(__nv_bfloat162*)(d + 2) = __floats2bfloat162_rn(wreg[p].z, wreg[p].w);
        }
        if (it < 15) {
#pragma unroll
            for (int p = 0; p < 4; p++) {
                int n = n0 + p * 32 + lrow;
                wreg[p] = (n < VOCAB)
                    ? *(const float4*)(W + (size_t)n * HH + (it + 1) * 32 + lq * 4)
                    : make_float4(0.f, 0.f, 0.f, 0.f);
            }
        }
        __syncthreads();
#pragma unroll
        for (int kk = 0; kk < 32; kk += 16) {
            wmma::fragment<wmma::matrix_b, 16, 16, 16, __nv_bfloat16, wmma::col_major> bf;
            wmma::load_matrix_sync(bf, wd + (warp * 16) * 40 + kk, 40);
#pragma unroll
            for (int i = 0; i < 2; i++) {
                wmma::fragment<wmma::matrix_a, 16, 16, 16, __nv_bfloat16, wmma::row_major> af;
                wmma::load_matrix_sync(af, As2 + (i * 16) * 520 + it * 32 + kk, 520);
                wmma::mma_sync(acc[i], af, bf, acc[i]);
            }
        }
        __syncthreads();
    }
#pragma unroll
    for (int i = 0; i < 2; i++)
        wmma::store_matrix_sync(stage + (i * 16) * 136 + warp * 16, acc[i], 136,
                                wmma::mem_row_major);
    __syncthreads();
    for (int idx = tid; idx < 32 * 128; idx += 256) {
        int r = idx >> 7, c = idx & 127;
        int n = n0 + c;
        if (n < VOCAB)
            g_logits[(size_t)r * VOCAB + n] = stage[r * 136 + c] + bias[n];
    }
}

// ---------------- softmax over V per b --------------------------------------
__global__ void k_softmaxV(float* __restrict__ out_fd) {
    __shared__ float red[32];
    int b = blockIdx.x, tid = threadIdx.x;     // 512 threads
    const float* lg = g_logits + (size_t)b * VOCAB;
    float* dst = out_fd + (size_t)b * VOCAB;

    float m = -1e30f;
    for (int n = tid; n < VOCAB; n += 512) m = fmaxf(m, lg[n]);
#pragma unroll
    for (int o = 16; o; o >>= 1) m = fmaxf(m, __shfl_xor_sync(0xffffffffu, m, o));
    if ((tid & 31) == 0) red[tid >> 5] = m;
    __syncthreads();
    if (tid < 32) {
        float v = (tid < 16) ? red[tid] : -1e30f;
#pragma unroll
        for (int o = 16; o; o >>= 1) v = fmaxf(v, __shfl_xor_sync(0xffffffffu, v, o));
        if (tid == 0) red[0] = v;
    }
    __syncthreads();
    float mx = red[0];
    __syncthreads();
    float s = 0.f;
    for (int n = tid; n < VOCAB; n += 512) {
        float e = __expf(lg[n] - mx);
        dst[n] = e;
        s += e;
    }
#pragma unroll
    for (int o = 16; o; o >>= 1) s += __shfl_xor_sync(0xffffffffu, s, o);
    if ((tid & 31) == 0) red[tid >> 5] = s;
    __syncthreads();
    if (tid < 32) {
        float v = (tid < 16) ? red[tid] : 0.f;
#pragma unroll
        for (int o = 16; o; o >>= 1) v += __shfl_xor_sync(0xffffffffu, v, o);
        if (tid == 0) red[0] = v;
    }
    __syncthreads();
    float inv = 1.f / red[0];
    for (int n = tid; n < VOCAB; n += 512) dst[n] *= inv;
}

// ---------------- launcher ---------------------------------------------------
extern "C" void kernel_launch(void* const* d_in, const int* in_sizes, int n_in,
                              void* d_out, int out_size) {
    const int*   y      = (const int*)d_in[0];
    const float* s_t_1  = (const float*)d_in[2];
    const float* enc    = (const float*)d_in[3];
    const float* c_t_1  = (const float*)d_in[4];
    const float* cov    = (const float*)d_in[5];
    const float* emb    = (const float*)d_in[7];
    const float* xc_w   = (const float*)d_in[8];
    const float* xc_b   = (const float*)d_in[9];
    const float* Wh_w   = (const float*)d_in[10];
    const float* w_ih   = (const float*)d_in[11];
    const float* w_hh   = (const float*)d_in[12];
    const float* b_ih   = (const float*)d_in[13];
    const float* b_hh   = (const float*)d_in[14];
    const float* dp_w   = (const float*)d_in[15];
    const float* dp_b   = (const float*)d_in[16];
    const float* v_w    = (const float*)d_in[17];
    const float* out1_w = (const float*)d_in[18];
    const float* out1_b = (const float*)d_in[19];
    const float* out2_w = (const float*)d_in[20];
    const float* out2_b = (const float*)d_in[21];

    float* out      = (float*)d_out;
    float* out_fd   = out;
    float* out_st   = out_fd + (size_t)BB * VOCAB;
    float* out_ct   = out_st + BB * HH;
    float* out_attn = out_ct + BB * HH;
    float* out_cov  = out_attn + BB * TKK;

    float *p_concatT, *p_out1;
    cudaGetSymbolAddress((void**)&p_concatT, g_concatT);
    cudaGetSymbolAddress((void**)&p_out1,    g_out1);

    cudaFuncSetAttribute(k_fused_attn, cudaFuncAttributeMaxDynamicSharedMemorySize, FA_SMEM);
    cudaFuncSetAttribute(k_logits_mma, cudaFuncAttributeMaxDynamicSharedMemorySize, LG_SMEM);

    // whole front-end in one persistent kernel
    k_frontend<<<FE_BLOCKS, FE_THREADS>>>(y, c_t_1, s_t_1, emb,
                                          xc_w, xc_b, w_ih, b_ih, w_hh, b_hh,
                                          dp_w, dp_b, out1_b, Wh_w, out_st);
    // fused attention scores
    k_fused_attn<<<M_ENC / 64, 512, FA_SMEM>>>(enc, v_w);
    k_attn<<<BB, 1024>>>(out_attn);
    k_ct_part<<<dim3(16, BB), 512>>>(enc, out_attn);
    k_ct_fin<<<BB, 512>>>(out_ct);
    // out1 = concat @ out1_w^T (N=512, K=1024, splits=8)
    k_bsplit<<<dim3(HH / 8, 8), 256>>>(nullptr, p_out1, p_concatT, out1_w, HH, 2 * HH);
    k_logits_mma<<<(VOCAB + 127) / 128, 256, LG_SMEM>>>(out2_w, out2_b);
    k_softmaxV<<<BB, 512>>>(out_fd);
    cudaMemcpyAsync(out_cov, cov, (size_t)BB * TKK * sizeof(float),
                    cudaMemcpyDeviceToDevice, 0);
}

// round 8
// speedup vs baseline: 1.1192x; 1.1118x over previous
#include <cuda_runtime.h>
#include <cuda_bf16.h>
#include <mma.h>
#include <cstddef>
#include <cstdint>

using namespace nvcuda;

#define BB    32
#define TKK   1024
#define HH    512
#define EE    256
#define VOCAB 50257
#define M_ENC (BB * TKK)   // 32768

#define FE_BLOCKS 256
#define FE_THREADS 256
#define FE_NT (FE_BLOCKS * FE_THREADS)

// ---------------- scratch (__device__ globals) ------------------------------
__device__ float g_xinT[(HH + EE) * BB];
__device__ float g_hT[HH * BB];
__device__ float g_xT[EE * BB];
__device__ float g_giT[3 * HH * BB];
__device__ float g_ghT[3 * HH * BB];
__device__ float g_hnewT[HH * BB];
__device__ float g_dec[BB * HH];
__device__ float g_scores[BB * TKK];
__device__ float g_cpart[BB * 16 * HH];
__device__ float g_concatT[2 * HH * BB];
__device__ float g_out1[BB * HH];
__device__ float g_logits[(size_t)BB * VOCAB];
__device__ __nv_bfloat16 g_whb[HH * HH];      // bf16 Wh, [n][k]
__device__ float g_smx[BB * 16];
__device__ float g_sms[BB * 16];

__device__ unsigned g_barcnt = 0;
__device__ unsigned g_barsense = 0;

__device__ __forceinline__ float sigmoidf_(float x) { return 1.f / (1.f + __expf(-x)); }
__device__ __forceinline__ float tanh_fast(float x) {
    float r; asm("tanh.approx.f32 %0, %1;" : "=f"(r) : "f"(x)); return r;
}
__device__ __forceinline__ void cp16(uint32_t dst, const void* src) {
    asm volatile("cp.async.cg.shared.global [%0], [%1], 16;" :: "r"(dst), "l"(src));
}
__device__ __forceinline__ void cp_commit() { asm volatile("cp.async.commit_group;"); }
template<int N> __device__ __forceinline__ void cp_wait() {
    asm volatile("cp.async.wait_group %0;" :: "n"(N));
}
__device__ __forceinline__ uint32_t packbf(float a, float b) {
    __nv_bfloat162 t = __floats2bfloat162_rn(a, b);
    return *(uint32_t*)&t;
}

// ---------------- grid-wide barrier -----------------------------------------
__device__ __forceinline__ void grid_bar(unsigned* sense) {
    __syncthreads();
    if (threadIdx.x == 0) {
        __threadfence();
        unsigned target = *sense ^ 1u;
        if (atomicAdd(&g_barcnt, 1u) == FE_BLOCKS - 1) {
            atomicExch(&g_barcnt, 0u);
            __threadfence();
            atomicExch(&g_barsense, target);
        } else {
            while (atomicAdd(&g_barsense, 0u) != target) {}
        }
        __threadfence();
        *sense = target;
    }
    __syncthreads();
}

__device__ __forceinline__ float dotk(const float4* __restrict__ w4,
                                      const float* __restrict__ a, int iters) {
    float a0 = 0.f, a1 = 0.f, a2 = 0.f, a3 = 0.f;
#pragma unroll 16
    for (int i = 0; i < iters; i++) {
        float4 w = w4[i];
        const float* ak = a + (i << 7);
        a0 += w.x * ak[0];
        a1 += w.y * ak[32];
        a2 += w.z * ak[64];
        a3 += w.w * ak[96];
    }
    return (a0 + a1) + (a2 + a3);
}

// ---------------- convert Wh -> bf16 (launch #0) ----------------------------
__global__ void k_convert_wh(const float* __restrict__ Wh) {
    int i = blockIdx.x * blockDim.x + threadIdx.x;
    float2 v = *(const float2*)(Wh + (size_t)i * 2);
    *(__nv_bfloat162*)(g_whb + (size_t)i * 2) = __floats2bfloat162_rn(v.x, v.y);
}

// ---------------- persistent front-end (launch #1) --------------------------
__global__ __launch_bounds__(FE_THREADS) void k_frontend(
    const int* __restrict__ yt, const float* __restrict__ c_t_1,
    const float* __restrict__ s_t_1, const float* __restrict__ emb,
    const float* __restrict__ xc_w, const float* __restrict__ xc_b,
    const float* __restrict__ w_ih, const float* __restrict__ b_ih,
    const float* __restrict__ w_hh, const float* __restrict__ b_hh,
    const float* __restrict__ dp_w, const float* __restrict__ dp_b,
    const float* __restrict__ out1_b,
    float* __restrict__ out_st)
{
    int tid = threadIdx.x;
    int gt = blockIdx.x * FE_THREADS + tid;
    int gw = gt >> 5, lane = gt & 31;
    unsigned sense = 0;
    if (tid == 0) sense = atomicAdd(&g_barsense, 0u);

    // ---- S0: bias init, transposes, zero scores ----
    for (int idx = gt; idx < 4352 * 32; idx += FE_NT) {
        int n = idx >> 5, b = idx & 31;
        if (n < EE)     { g_xT[n * 32 + b] = xc_b[n];  continue; }  n -= EE;
        if (n < 3 * HH) { g_giT[n * 32 + b] = b_ih[n]; continue; }  n -= 3 * HH;
        if (n < 3 * HH) { g_ghT[n * 32 + b] = b_hh[n]; continue; }  n -= 3 * HH;
        if (n < HH)     { g_dec[b * HH + n] = dp_b[n]; continue; }  n -= HH;
        g_out1[b * HH + n] = out1_b[n];
    }
    for (int idx = gt; idx < (HH + EE) * BB; idx += FE_NT) {
        int k = idx >> 5, b = idx & 31;
        g_xinT[idx] = (k < HH) ? c_t_1[b * HH + k]
                               : emb[(size_t)yt[b] * EE + (k - HH)];
    }
    for (int idx = gt; idx < HH * BB; idx += FE_NT) {
        int k = idx >> 5, b = idx & 31;
        g_hT[idx] = s_t_1[b * HH + k];
    }
    for (int idx = gt; idx < BB * TKK; idx += FE_NT) g_scores[idx] = 0.f;
    grid_bar(&sense);

    // ---- S1: x ----
    {
        int n = gw >> 3, sp = gw & 7;
        int k0 = sp * 96;
        float r = dotk((const float4*)(xc_w + (size_t)n * (HH + EE) + k0),
                       g_xinT + k0 * 32 + lane, 24);
        atomicAdd(&g_xT[n * 32 + lane], r);
    }
    grid_bar(&sense);

    // ---- S2: gi + gh ----
    for (int u = gw; u < 9216; u += 2048) {
        if (u < 3072) {
            int n = u >> 1, sp = u & 1, k0 = sp * 128;
            float r = dotk((const float4*)(w_ih + (size_t)n * EE + k0),
                           g_xT + k0 * 32 + lane, 32);
            atomicAdd(&g_giT[n * 32 + lane], r);
        } else {
            int v = u - 3072;
            int n = v >> 2, sp = v & 3, k0 = sp * 128;
            float r = dotk((const float4*)(w_hh + (size_t)n * HH + k0),
                           g_hT + k0 * 32 + lane, 32);
            atomicAdd(&g_ghT[n * 32 + lane], r);
        }
    }
    grid_bar(&sense);

    // ---- S3: GRU ----
    if (gt < HH * BB) {
        int j = gt >> 5, b = gt & 31;
        float ir = g_giT[j * BB + b],             hr = g_ghT[j * BB + b];
        float iz = g_giT[(HH + j) * BB + b],      hz = g_ghT[(HH + j) * BB + b];
        float in_ = g_giT[(2 * HH + j) * BB + b], hn = g_ghT[(2 * HH + j) * BB + b];
        float r = sigmoidf_(ir + hr);
        float z = sigmoidf_(iz + hz);
        float nn = tanhf(in_ + r * hn);
        float h = g_hT[j * BB + b];
        float hv = (1.f - z) * nn + z * h;
        g_hnewT[j * BB + b] = hv;
        g_concatT[j * BB + b] = hv;
        out_st[b * HH + j] = hv;
    }
    grid_bar(&sense);

    // ---- S4: dec ----
    {
        int n = gw >> 2, sp = gw & 3, k0 = sp * 128;
        float r = dotk((const float4*)(dp_w + (size_t)n * HH + k0),
                       g_hnewT + k0 * 32 + lane, 32);
        atomicAdd(&g_dec[lane * HH + n], r);
    }
}

// ---------------- split-K small GEMM (out1) ---------------------------------
__global__ __launch_bounds__(256) void k_bsplit(float* __restrict__ yT,
                                                float* __restrict__ yR,
                                                const float* __restrict__ AT,
                                                const float* __restrict__ W,
                                                int N, int K) {
    int warp = threadIdx.x >> 5, lane = threadIdx.x & 31;
    int n = blockIdx.x * 8 + warp;
    int kchunk = K / gridDim.y;
    int k0 = blockIdx.y * kchunk;
    float r = dotk((const float4*)(W + (size_t)n * K + k0),
                   AT + k0 * 32 + lane, kchunk >> 2);
    if (yT) atomicAdd(&yT[n * 32 + lane], r);
    if (yR) atomicAdd(&yR[(size_t)lane * N + n], r);
}

// ---------------- fused attention v2 (N-split halves) -----------------------
// Per block: D[64 rows, 256 cols] partial of enc@Wh^T; epilogue adds partial
// scores. smem: sdec(1K) sv(1K) srow(512B) As[2][64][40] Bs[3][256][40].
#define F2_SDEC   0
#define F2_SV     1024
#define F2_SROW   2048
#define F2_AS     2560
#define F2_BS     12800
#define F2_SMEM   74240
__global__ __launch_bounds__(256, 2) void k_fat2(const float* __restrict__ enc,
                                                 const float* __restrict__ vw,
                                                 int n0) {
    extern __shared__ char sm[];
    uint32_t smb = (uint32_t)__cvta_generic_to_shared(sm);
    float* sdec = (float*)(sm + F2_SDEC);
    float* sv   = (float*)(sm + F2_SV);
    float* srow = (float*)(sm + F2_SROW);
    __nv_bfloat16* As = (__nv_bfloat16*)(sm + F2_AS);   // [2][64*40]
    __nv_bfloat16* Bs = (__nv_bfloat16*)(sm + F2_BS);   // [3][256*40]

    int tid = threadIdx.x, warp = tid >> 5, lane = tid & 31;
    int bt = blockIdx.x;               // 0..511 (64-row tiles)
    int b  = bt >> 4;
    size_t m0 = (size_t)bt * 64;

    sv[tid]   = vw[n0 + tid];
    sdec[tid] = g_dec[b * HH + n0 + tid];
    if (tid < 64) srow[tid] = 0.f;

    int wm = warp >> 2, wn = warp & 3;     // 2 x 4 warp layout
    wmma::fragment<wmma::accumulator, 16, 16, 16, float> acc[2][4];
#pragma unroll
    for (int i = 0; i < 2; i++)
#pragma unroll
        for (int j = 0; j < 4; j++) wmma::fill_fragment(acc[i][j], 0.f);

    int arow = tid >> 2, aq = tid & 3;     // A: 64 rows x 4 octs (8 k each)

    // prologue: B chunk 0 (cp.async) + A chunk 0 (regs)
    {
#pragma unroll
        for (int q = 0; q < 4; q++)
            cp16(smb + F2_BS + (uint32_t)(tid * 80 + q * 16),
                 g_whb + (size_t)(n0 + tid) * HH + q * 8);
        cp_commit();
    }
    float4 a0r = *(const float4*)(enc + (m0 + arow) * HH + aq * 8);
    float4 a1r = *(const float4*)(enc + (m0 + arow) * HH + aq * 8 + 4);

    const int NIT = 16;   // K chunks of 32
    for (int it = 0; it < NIT; it++) {
        int c2 = it & 1, c3 = it - (it / 3) * 3;
        // prefetch B(it+1)
        if (it < NIT - 1) {
            int n3 = (it + 1) - ((it + 1) / 3) * 3;
#pragma unroll
            for (int q = 0; q < 4; q++)
                cp16(smb + F2_BS + (uint32_t)(n3 * 20480 + tid * 80 + q * 16),
                     g_whb + (size_t)(n0 + tid) * HH + (it + 1) * 32 + q * 8);
            cp_commit();
        }
        // store A(it) regs -> As[c2]
        {
            uint4 pk = make_uint4(packbf(a0r.x, a0r.y), packbf(a0r.z, a0r.w),
                                  packbf(a1r.x, a1r.y), packbf(a1r.z, a1r.w));
            *(uint4*)((char*)As + c2 * 5120 + arow * 80 + aq * 16) = pk;
        }
        // prefetch A(it+1)
        if (it < NIT - 1) {
            a0r = *(const float4*)(enc + (m0 + arow) * HH + (it + 1) * 32 + aq * 8);
            a1r = *(const float4*)(enc + (m0 + arow) * HH + (it + 1) * 32 + aq * 8 + 4);
        }
        if (it < NIT - 1) cp_wait<1>(); else cp_wait<0>();
        __syncthreads();
        const __nv_bfloat16* ab = (const __nv_bfloat16*)((char*)As + c2 * 5120);
        const __nv_bfloat16* bb = (const __nv_bfloat16*)((char*)Bs + c3 * 20480);
#pragma unroll
        for (int kk = 0; kk < 32; kk += 16) {
            wmma::fragment<wmma::matrix_a, 16, 16, 16, __nv_bfloat16, wmma::row_major> af[2];
#pragma unroll
            for (int i = 0; i < 2; i++)
                wmma::load_matrix_sync(af[i], ab + (wm * 32 + i * 16) * 40 + kk, 40);
#pragma unroll
            for (int j = 0; j < 4; j++) {
                wmma::fragment<wmma::matrix_b, 16, 16, 16, __nv_bfloat16, wmma::col_major> bf;
                wmma::load_matrix_sync(bf, bb + (wn * 64 + j * 16) * 40 + kk, 40);
                wmma::mma_sync(acc[0][j], af[0], bf, acc[0][j]);
                wmma::mma_sync(acc[1][j], af[1], bf, acc[1][j]);
            }
        }
        __syncthreads();
    }

    // epilogue: per-warp scratch (aliases As/Bs region), partial scores
    float* scr = (float*)(sm + F2_AS) + warp * 1088;    // [16][68]
#pragma unroll
    for (int i = 0; i < 2; i++) {
#pragma unroll
        for (int j = 0; j < 4; j++)
            wmma::store_matrix_sync(scr + j * 16, acc[i][j], 68, wmma::mem_row_major);
        __syncwarp();
        int row = lane >> 1, half = lane & 1;
        const float* sr = scr + row * 68;
        float p = 0.f;
#pragma unroll
        for (int c = 0; c < 32; c++) {
            int cl = wn * 64 + half * 32 + c;
            p += sv[cl] * tanh_fast(sr[half * 32 + c] + sdec[cl]);
        }
        p += __shfl_xor_sync(0xffffffffu, p, 1);
        if (half == 0) atomicAdd(&srow[wm * 32 + i * 16 + row], p);
        __syncwarp();
    }
    __syncthreads();
    if (tid < 64) atomicAdd(&g_scores[bt * 64 + tid], srow[tid]);
}

// ---------------- softmax over TK per b -------------------------------------
__global__ void k_attn(float* __restrict__ out_attn) {
    __shared__ float red[32];
    int b = blockIdx.x, t = threadIdx.x;   // 1024 threads
    float s = g_scores[b * TKK + t];
    float m = s;
#pragma unroll
    for (int o = 16; o; o >>= 1) m = fmaxf(m, __shfl_xor_sync(0xffffffffu, m, o));
    if ((t & 31) == 0) red[t >> 5] = m;
    __syncthreads();
    if (t < 32) {
        float v = red[t];
#pragma unroll
        for (int o = 16; o; o >>= 1) v = fmaxf(v, __shfl_xor_sync(0xffffffffu, v, o));
        if (t == 0) red[0] = v;
    }
    __syncthreads();
    float mx = red[0];
    __syncthreads();
    float e = __expf(s - mx);
    float sm = e;
#pragma unroll
    for (int o = 16; o; o >>= 1) sm += __shfl_xor_sync(0xffffffffu, sm, o);
    if ((t & 31) == 0) red[t >> 5] = sm;
    __syncthreads();
    if (t < 32) {
        float v = red[t];
#pragma unroll
        for (int o = 16; o; o >>= 1) v += __shfl_xor_sync(0xffffffffu, v, o);
        if (t == 0) red[0] = v;
    }
    __syncthreads();
    out_attn[b * TKK + t] = e * (1.f / red[0]);
}

// ---------------- c_t partials ----------------------------------------------
__global__ void k_ct_part(const float* __restrict__ enc, const float* __restrict__ attn) {
    __shared__ float sa[64];
    int c = blockIdx.x, b = blockIdx.y, h = threadIdx.x;   // 512 threads
    if (h < 64) sa[h] = attn[b * TKK + c * 64 + h];
    __syncthreads();
    const float* e = enc + ((size_t)b * TKK + c * 64) * HH + h;
    float acc = 0.f;
#pragma unroll 8
    for (int t = 0; t < 64; t++) acc += sa[t] * e[(size_t)t * HH];
    g_cpart[((size_t)b * 16 + c) * HH + h] = acc;
}

__global__ void k_ct_fin(float* __restrict__ out_ct) {
    int b = blockIdx.x, h = threadIdx.x;   // 512
    float acc = 0.f;
#pragma unroll
    for (int c = 0; c < 16; c++) acc += g_cpart[((size_t)b * 16 + c) * HH + h];
    out_ct[b * HH + h] = acc;
    g_concatT[(HH + h) * BB + b] = acc;
}

// ---------------- logits via wmma, double buffered --------------------------
#define LG_SMEM (33280 + 20480)
__global__ __launch_bounds__(256) void k_logits_mma(const float* __restrict__ W,
                                                    const float* __restrict__ bias) {
    extern __shared__ char smraw[];
    __nv_bfloat16* As2 = (__nv_bfloat16*)smraw;                // [32][520]
    __nv_bfloat16* Ws  = (__nv_bfloat16*)(smraw + 33280);      // [2][128][40]
    float* stage = (float*)(smraw + 33280);                    // [32][136]

    int tid = threadIdx.x, warp = tid >> 5;
    int n0 = blockIdx.x * 128;
    for (int idx = tid; idx < BB * HH; idx += 256) {
        int r = idx >> 9, k = idx & 511;
        As2[r * 520 + k] = __float2bfloat16(g_out1[idx]);
    }

    wmma::fragment<wmma::accumulator, 16, 16, 16, float> acc[2];
    wmma::fill_fragment(acc[0], 0.f);
    wmma::fill_fragment(acc[1], 0.f);

    int lrow = tid >> 3, lq = tid & 7;
    float4 wreg[4];
#pragma unroll
    for (int p = 0; p < 4; p++) {
        int n = n0 + p * 32 + lrow;
        wreg[p] = (n < VOCAB) ? *(const float4*)(W + (size_t)n * HH + lq * 4)
                              : make_float4(0.f, 0.f, 0.f, 0.f);
    }
    for (int it = 0; it < 16; it++) {
        int cur = it & 1;
        __nv_bfloat16* wd = Ws + cur * (128 * 40);
#pragma unroll
        for (int p = 0; p < 4; p++) {
            __nv_bfloat16* d = wd + (p * 32 + lrow) * 40 + lq * 4;
            *(__nv_bfloat162*)d       = __floats2bfloat162_rn(wreg[p].x, wreg[p].y);
            *(__nv_bfloat162*)(d + 2) = __floats2bfloat162_rn(wreg[p].z, wreg[p].w);
        }
        if (it < 15) {
#pragma unroll
            for (int p = 0; p < 4; p++) {
                int n = n0 + p * 32 + lrow;
                wreg[p] = (n < VOCAB)
                    ? *(const float4*)(W + (size_t)n * HH + (it + 1) * 32 + lq * 4)
                    : make_float4(0.f, 0.f, 0.f, 0.f);
            }
        }
        __syncthreads();
#pragma unroll
        for (int kk = 0; kk < 32; kk += 16) {
            wmma::fragment<wmma::matrix_b, 16, 16, 16, __nv_bfloat16, wmma::col_major> bf;
            wmma::load_matrix_sync(bf, wd + (warp * 16) * 40 + kk, 40);
#pragma unroll
            for (int i = 0; i < 2; i++) {
                wmma::fragment<wmma::matrix_a, 16, 16, 16, __nv_bfloat16, wmma::row_major> af;
                wmma::load_matrix_sync(af, As2 + (i * 16) * 520 + it * 32 + kk, 520);
                wmma::mma_sync(acc[i], af, bf, acc[i]);
            }
        }
        __syncthreads();
    }
#pragma unroll
    for (int i = 0; i < 2; i++)
        wmma::store_matrix_sync(stage + (i * 16) * 136 + warp * 16, acc[i], 136,
                                wmma::mem_row_major);
    __syncthreads();
    for (int idx = tid; idx < 32 * 128; idx += 256) {
        int r = idx >> 7, c = idx & 127;
        int n = n0 + c;
        if (n < VOCAB)
            g_logits[(size_t)r * VOCAB + n] = stage[r * 136 + c] + bias[n];
    }
}

// ---------------- parallel vocab softmax: partials then normalize -----------
#define SM_CH 3142
__global__ void k_smA() {
    __shared__ float red[32];
    int b = blockIdx.y, slab = blockIdx.x, tid = threadIdx.x;   // 256 thr
    int start = slab * SM_CH;
    int end = min(start + SM_CH, VOCAB);
    const float* lg = g_logits + (size_t)b * VOCAB;

    float m = -1e30f;
    for (int n = start + tid; n < end; n += 256) m = fmaxf(m, lg[n]);
#pragma unroll
    for (int o = 16; o; o >>= 1) m = fmaxf(m, __shfl_xor_sync(0xffffffffu, m, o));
    if ((tid & 31) == 0) red[tid >> 5] = m;
    __syncthreads();
    if (tid < 32) {
        float v = (tid < 8) ? red[tid] : -1e30f;
#pragma unroll
        for (int o = 4; o; o >>= 1) v = fmaxf(v, __shfl_xor_sync(0xffffffffu, v, o));
        if (tid == 0) red[0] = v;
    }
    __syncthreads();
    float mx = red[0];
    __syncthreads();
    float s = 0.f;
    for (int n = start + tid; n < end; n += 256) s += __expf(lg[n] - mx);
#pragma unroll
    for (int o = 16; o; o >>= 1) s += __shfl_xor_sync(0xffffffffu, s, o);
    if ((tid & 31) == 0) red[tid >> 5] = s;
    __syncthreads();
    if (tid < 32) {
        float v = (tid < 8) ? red[tid] : 0.f;
#pragma unroll
        for (int o = 4; o; o >>= 1) v += __shfl_xor_sync(0xffffffffu, v, o);
        if (tid == 0) {
            g_smx[b * 16 + slab] = mx;
            g_sms[b * 16 + slab] = v;
        }
    }
}

__global__ void k_smB(float* __restrict__ out_fd) {
    int b = blockIdx.y, tid = threadIdx.x;    // 256 thr, grid (25, 32)
    float M = -1e30f;
#pragma unroll
    for (int i = 0; i < 16; i++) M = fmaxf(M, g_smx[b * 16 + i]);
    float S = 0.f;
#pragma unroll
    for (int i = 0; i < 16; i++) S += g_sms[b * 16 + i] * __expf(g_smx[b * 16 + i] - M);
    float inv = 1.f / S;
    const float* lg = g_logits + (size_t)b * VOCAB;
    float* dst = out_fd + (size_t)b * VOCAB;
    int base = blockIdx.x * 2048;
#pragma unroll
    for (int j = 0; j < 8; j++) {
        int n = base + j * 256 + tid;
        if (n < VOCAB) dst[n] = __expf(lg[n] - M) * inv;
    }
}

// ---------------- launcher ---------------------------------------------------
extern "C" void kernel_launch(void* const* d_in, const int* in_sizes, int n_in,
                              void* d_out, int out_size) {
    const int*   y      = (const int*)d_in[0];
    const float* s_t_1  = (const float*)d_in[2];
    const float* enc    = (const float*)d_in[3];
    const float* c_t_1  = (const float*)d_in[4];
    const float* cov    = (const float*)d_in[5];
    const float* emb    = (const float*)d_in[7];
    const float* xc_w   = (const float*)d_in[8];
    const float* xc_b   = (const float*)d_in[9];
    const float* Wh_w   = (const float*)d_in[10];
    const float* w_ih   = (const float*)d_in[11];
    const float* w_hh   = (const float*)d_in[12];
    const float* b_ih   = (const float*)d_in[13];
    const float* b_hh   = (const float*)d_in[14];
    const float* dp_w   = (const float*)d_in[15];
    const float* dp_b   = (const float*)d_in[16];
    const float* v_w    = (const float*)d_in[17];
    const float* out1_w = (const float*)d_in[18];
    const float* out1_b = (const float*)d_in[19];
    const float* out2_w = (const float*)d_in[20];
    const float* out2_b = (const float*)d_in[21];

    float* out      = (float*)d_out;
    float* out_fd   = out;
    float* out_st   = out_fd + (size_t)BB * VOCAB;
    float* out_ct   = out_st + BB * HH;
    float* out_attn = out_ct + BB * HH;
    float* out_cov  = out_attn + BB * TKK;

    float *p_concatT, *p_out1;
    cudaGetSymbolAddress((void**)&p_concatT, g_concatT);
    cudaGetSymbolAddress((void**)&p_out1,    g_out1);

    cudaFuncSetAttribute(k_fat2, cudaFuncAttributeMaxDynamicSharedMemorySize, F2_SMEM);
    cudaFuncSetAttribute(k_logits_mma, cudaFuncAttributeMaxDynamicSharedMemorySize, LG_SMEM);

    k_convert_wh<<<512, 256>>>(Wh_w);                                      // 0
    k_frontend<<<FE_BLOCKS, FE_THREADS>>>(y, c_t_1, s_t_1, emb,
                                          xc_w, xc_b, w_ih, b_ih, w_hh, b_hh,
                                          dp_w, dp_b, out1_b, out_st);     // 1
    k_fat2<<<M_ENC / 64, 256, F2_SMEM>>>(enc, v_w, 0);                     // 2
    k_fat2<<<M_ENC / 64, 256, F2_SMEM>>>(enc, v_w, 256);                   // 3 <- profiled
    k_attn<<<BB, 1024>>>(out_attn);                                        // 4
    k_ct_part<<<dim3(16, BB), 512>>>(enc, out_attn);                       // 5
    k_ct_fin<<<BB, 512>>>(out_ct);                                         // 6
    k_bsplit<<<dim3(HH / 8, 8), 256>>>(nullptr, p_out1, p_concatT, out1_w, HH, 2 * HH);
    k_logits_mma<<<(VOCAB + 127) / 128, 256, LG_SMEM>>>(out2_w, out2_b);
    k_smA<<<dim3(16, BB), 256>>>();
    k_smB<<<dim3(25, BB), 256>>>(out_fd);
    cudaMemcpyAsync(out_cov, cov, (size_t)BB * TKK * sizeof(float),
                    cudaMemcpyDeviceToDevice, 0);
}

// round 9
// speedup vs baseline: 1.3157x; 1.1756x over previous
#include <cuda_runtime.h>
#include <cuda_bf16.h>
#include <cuda_fp16.h>
#include <mma.h>
#include <cstddef>
#include <cstdint>

using namespace nvcuda;

#define BB    32
#define TKK   1024
#define HH    512
#define EE    256
#define VOCAB 50257
#define M_ENC (BB * TKK)   // 32768

#define FE_BLOCKS 256
#define FE_THREADS 256
#define FE_NT (FE_BLOCKS * FE_THREADS)

// ---------------- scratch (__device__ globals) ------------------------------
__device__ float g_xinT[(HH + EE) * BB];
__device__ float g_hT[HH * BB];
__device__ float g_xT[EE * BB];
__device__ float g_giT[3 * HH * BB];
__device__ float g_ghT[3 * HH * BB];
__device__ float g_hnewT[HH * BB];
__device__ float g_dec[BB * HH];
__device__ float g_scores[BB * TKK];
__device__ float g_cpart[BB * 16 * HH];
__device__ float g_concatT[2 * HH * BB];
__device__ float g_out1[BB * HH];
__device__ float g_logits[(size_t)BB * VOCAB];
__device__ __half g_whh[HH * HH];                 // fp16 Wh [n][k]
__device__ __half g_ench[(size_t)M_ENC * HH];     // fp16 enc
__device__ float g_smx[BB * 16];
__device__ float g_sms[BB * 16];

__device__ unsigned g_barcnt = 0;
__device__ unsigned g_barsense = 0;

__device__ __forceinline__ float sigmoidf_(float x) { return 1.f / (1.f + __expf(-x)); }
__device__ __forceinline__ float tanh_fast(float x) {
    float r; asm("tanh.approx.f32 %0, %1;" : "=f"(r) : "f"(x)); return r;
}
__device__ __forceinline__ void cp16(uint32_t dst, const void* src) {
    asm volatile("cp.async.cg.shared.global [%0], [%1], 16;" :: "r"(dst), "l"(src));
}
__device__ __forceinline__ void cp_commit() { asm volatile("cp.async.commit_group;"); }
template<int N> __device__ __forceinline__ void cp_wait() {
    asm volatile("cp.async.wait_group %0;" :: "n"(N));
}
__device__ __forceinline__ uint32_t packh(float a, float b) {
    __half2 t = __floats2half2_rn(a, b);
    return *(uint32_t*)&t;
}

// ---------------- grid-wide barrier -----------------------------------------
__device__ __forceinline__ void grid_bar(unsigned* sense) {
    __syncthreads();
    if (threadIdx.x == 0) {
        __threadfence();
        unsigned target = *sense ^ 1u;
        if (atomicAdd(&g_barcnt, 1u) == FE_BLOCKS - 1) {
            atomicExch(&g_barcnt, 0u);
            __threadfence();
            atomicExch(&g_barsense, target);
        } else {
            while (atomicAdd(&g_barsense, 0u) != target) {}
        }
        __threadfence();
        *sense = target;
    }
    __syncthreads();
}

__device__ __forceinline__ float dotk(const float4* __restrict__ w4,
                                      const float* __restrict__ a, int iters) {
    float a0 = 0.f, a1 = 0.f, a2 = 0.f, a3 = 0.f;
#pragma unroll 16
    for (int i = 0; i < iters; i++) {
        float4 w = w4[i];
        const float* ak = a + (i << 7);
        a0 += w.x * ak[0];
        a1 += w.y * ak[32];
        a2 += w.z * ak[64];
        a3 += w.w * ak[96];
    }
    return (a0 + a1) + (a2 + a3);
}

// ---------------- convert Wh -> fp16 (launch #0) ----------------------------
__global__ void k_convert_wh(const float* __restrict__ Wh) {
    int i = blockIdx.x * blockDim.x + threadIdx.x;      // 131072 pairs
    float2 v = *(const float2*)(Wh + (size_t)i * 2);
    *(__half2*)(g_whh + (size_t)i * 2) = __floats2half2_rn(v.x, v.y);
}

// ---------------- convert enc -> fp16 (launch #1) ---------------------------
__global__ void k_convert_enc(const float* __restrict__ enc) {
    size_t i = (size_t)blockIdx.x * blockDim.x + threadIdx.x;  // 2097152, 8 elems each
    const float4* s = (const float4*)(enc) + i * 2;
    float4 v0 = s[0], v1 = s[1];
    *(uint4*)(g_ench + i * 8) = make_uint4(packh(v0.x, v0.y), packh(v0.z, v0.w),
                                           packh(v1.x, v1.y), packh(v1.z, v1.w));
}

// ---------------- persistent front-end (launch #2) --------------------------
__global__ __launch_bounds__(FE_THREADS) void k_frontend(
    const int* __restrict__ yt, const float* __restrict__ c_t_1,
    const float* __restrict__ s_t_1, const float* __restrict__ emb,
    const float* __restrict__ xc_w, const float* __restrict__ xc_b,
    const float* __restrict__ w_ih, const float* __restrict__ b_ih,
    const float* __restrict__ w_hh, const float* __restrict__ b_hh,
    const float* __restrict__ dp_w, const float* __restrict__ dp_b,
    const float* __restrict__ out1_b,
    float* __restrict__ out_st)
{
    int tid = threadIdx.x;
    int gt = blockIdx.x * FE_THREADS + tid;
    int gw = gt >> 5, lane = gt & 31;
    unsigned sense = 0;
    if (tid == 0) sense = atomicAdd(&g_barsense, 0u);

    for (int idx = gt; idx < 4352 * 32; idx += FE_NT) {
        int n = idx >> 5, b = idx & 31;
        if (n < EE)     { g_xT[n * 32 + b] = xc_b[n];  continue; }  n -= EE;
        if (n < 3 * HH) { g_giT[n * 32 + b] = b_ih[n]; continue; }  n -= 3 * HH;
        if (n < 3 * HH) { g_ghT[n * 32 + b] = b_hh[n]; continue; }  n -= 3 * HH;
        if (n < HH)     { g_dec[b * HH + n] = dp_b[n]; continue; }  n -= HH;
        g_out1[b * HH + n] = out1_b[n];
    }
    for (int idx = gt; idx < (HH + EE) * BB; idx += FE_NT) {
        int k = idx >> 5, b = idx & 31;
        g_xinT[idx] = (k < HH) ? c_t_1[b * HH + k]
                               : emb[(size_t)yt[b] * EE + (k - HH)];
    }
    for (int idx = gt; idx < HH * BB; idx += FE_NT) {
        int k = idx >> 5, b = idx & 31;
        g_hT[idx] = s_t_1[b * HH + k];
    }
    for (int idx = gt; idx < BB * TKK; idx += FE_NT) g_scores[idx] = 0.f;
    grid_bar(&sense);

    {
        int n = gw >> 3, sp = gw & 7;
        int k0 = sp * 96;
        float r = dotk((const float4*)(xc_w + (size_t)n * (HH + EE) + k0),
                       g_xinT + k0 * 32 + lane, 24);
        atomicAdd(&g_xT[n * 32 + lane], r);
    }
    grid_bar(&sense);

    for (int u = gw; u < 9216; u += 2048) {
        if (u < 3072) {
            int n = u >> 1, sp = u & 1, k0 = sp * 128;
            float r = dotk((const float4*)(w_ih + (size_t)n * EE + k0),
                           g_xT + k0 * 32 + lane, 32);
            atomicAdd(&g_giT[n * 32 + lane], r);
        } else {
            int v = u - 3072;
            int n = v >> 2, sp = v & 3, k0 = sp * 128;
            float r = dotk((const float4*)(w_hh + (size_t)n * HH + k0),
                           g_hT + k0 * 32 + lane, 32);
            atomicAdd(&g_ghT[n * 32 + lane], r);
        }
    }
    grid_bar(&sense);

    if (gt < HH * BB) {
        int j = gt >> 5, b = gt & 31;
        float ir = g_giT[j * BB + b],             hr = g_ghT[j * BB + b];
        float iz = g_giT[(HH + j) * BB + b],      hz = g_ghT[(HH + j) * BB + b];
        float in_ = g_giT[(2 * HH + j) * BB + b], hn = g_ghT[(2 * HH + j) * BB + b];
        float r = sigmoidf_(ir + hr);
        float z = sigmoidf_(iz + hz);
        float nn = tanhf(in_ + r * hn);
        float h = g_hT[j * BB + b];
        float hv = (1.f - z) * nn + z * h;
        g_hnewT[j * BB + b] = hv;
        g_concatT[j * BB + b] = hv;
        out_st[b * HH + j] = hv;
    }
    grid_bar(&sense);

    {
        int n = gw >> 2, sp = gw & 3, k0 = sp * 128;
        float r = dotk((const float4*)(dp_w + (size_t)n * HH + k0),
                       g_hnewT + k0 * 32 + lane, 32);
        atomicAdd(&g_dec[lane * HH + n], r);
    }
}

// ---------------- split-K small GEMM (out1) ---------------------------------
__global__ __launch_bounds__(256) void k_bsplit(float* __restrict__ yT,
                                                float* __restrict__ yR,
                                                const float* __restrict__ AT,
                                                const float* __restrict__ W,
                                                int N, int K) {
    int warp = threadIdx.x >> 5, lane = threadIdx.x & 31;
    int n = blockIdx.x * 8 + warp;
    int kchunk = K / gridDim.y;
    int k0 = blockIdx.y * kchunk;
    float r = dotk((const float4*)(W + (size_t)n * K + k0),
                   AT + k0 * 32 + lane, kchunk >> 2);
    if (yT) atomicAdd(&yT[n * 32 + lane], r);
    if (yR) atomicAdd(&yR[(size_t)lane * N + n], r);
}

// ---------------- fused attention v3 (launch #3, profiled) ------------------
// grid (512, 2): blockIdx.x = 64-row M tile, blockIdx.y = 256-col N half.
// fp16 inputs + fp16 acc; both operands via cp.async; ONE barrier per k-iter.
// smem: sdec[256] sv[256] srow[64] | 2 stages x (A 64x(32k,pad40) + B 256x(32k,pad40))
#define F3_STG   2304
#define F3_STGSZ 25600
#define F3_SMEM  (F3_STG + 2 * F3_STGSZ)     // 53504

#define F3_ISSUE(c, st) do {                                                    \
    uint32_t sb_ = smb + F3_STG + (st) * F3_STGSZ;                              \
    _Pragma("unroll")                                                           \
    for (int i_ = 0; i_ < 5; i_++) {                                            \
        int s_ = tid + (i_ << 8);                                               \
        if (i_ == 0) {                                                          \
            int r_ = s_ >> 2, q_ = s_ & 3;                                      \
            cp16(sb_ + r_ * 80 + q_ * 16,                                       \
                 g_ench + (m0 + r_) * HH + (c) * 32 + q_ * 8);                  \
        } else {                                                                \
            int t_ = s_ - 256, r_ = t_ >> 2, q_ = t_ & 3;                       \
            cp16(sb_ + 5120 + r_ * 80 + q_ * 16,                                \
                 g_whh + (size_t)(n0 + r_) * HH + (c) * 32 + q_ * 8);           \
        }                                                                       \
    }                                                                           \
    cp_commit();                                                                \
} while (0)

__global__ __launch_bounds__(256, 3) void k_fat3(const float* __restrict__ vw) {
    extern __shared__ char sm[];
    uint32_t smb = (uint32_t)__cvta_generic_to_shared(sm);
    float* sdec = (float*)(sm + 0);
    float* sv   = (float*)(sm + 1024);
    float* srow = (float*)(sm + 2048);

    int tid = threadIdx.x, warp = tid >> 5, lane = tid & 31;
    int bt = blockIdx.x, n0 = blockIdx.y << 8;
    int b = bt >> 4;
    size_t m0 = (size_t)bt * 64;

    sv[tid]   = vw[n0 + tid];
    sdec[tid] = g_dec[b * HH + n0 + tid];
    if (tid < 64) srow[tid] = 0.f;

    int wm = warp >> 2, wn = warp & 3;    // warp tile: 32 rows x 64 cols
    wmma::fragment<wmma::accumulator, 16, 16, 16, __half> acc[2][4];
#pragma unroll
    for (int i = 0; i < 2; i++)
#pragma unroll
        for (int j = 0; j < 4; j++) wmma::fill_fragment(acc[i][j], __float2half(0.f));

    F3_ISSUE(0, 0);

    for (int c = 0; c < 16; c++) {
        cp_wait<0>();
        __syncthreads();     // publishes stage c; retires stage c-1 (all mma done)
        if (c < 15) F3_ISSUE(c + 1, (c + 1) & 1);
        const __half* ab = (const __half*)(sm + F3_STG + (c & 1) * F3_STGSZ);
        const __half* bb = ab + 2560;
#pragma unroll
        for (int kk = 0; kk < 32; kk += 16) {
            wmma::fragment<wmma::matrix_a, 16, 16, 16, __half, wmma::row_major> af[2];
#pragma unroll
            for (int i = 0; i < 2; i++)
                wmma::load_matrix_sync(af[i], ab + (wm * 32 + i * 16) * 40 + kk, 40);
#pragma unroll
            for (int j = 0; j < 4; j++) {
                wmma::fragment<wmma::matrix_b, 16, 16, 16, __half, wmma::col_major> bf;
                wmma::load_matrix_sync(bf, bb + (wn * 64 + j * 16) * 40 + kk, 40);
                wmma::mma_sync(acc[0][j], af[0], bf, acc[0][j]);
                wmma::mma_sync(acc[1][j], af[1], bf, acc[1][j]);
            }
        }
    }
    __syncthreads();   // protect stage buffers before scratch reuse

    // epilogue: per-warp half scratch in stage region
    __half* scr = (__half*)(sm + F3_STG) + warp * 1088;   // [16][68] halfs
#pragma unroll
    for (int i = 0; i < 2; i++) {
#pragma unroll
        for (int j = 0; j < 4; j++)
            wmma::store_matrix_sync(scr + j * 16, acc[i][j], 68, wmma::mem_row_major);
        __syncwarp();
        int row = lane >> 1, hf = lane & 1;
        const __half* sr = scr + row * 68;
        float p = 0.f;
#pragma unroll
        for (int c = 0; c < 32; c++) {
            int cl = wn * 64 + hf * 32 + c;
            p += sv[cl] * tanh_fast(__half2float(sr[hf * 32 + c]) + sdec[cl]);
        }
        p += __shfl_xor_sync(0xffffffffu, p, 1);
        if (hf == 0) atomicAdd(&srow[wm * 32 + i * 16 + row], p);
        __syncwarp();
    }
    __syncthreads();
    if (tid < 64) atomicAdd(&g_scores[bt * 64 + tid], srow[tid]);
}

// ---------------- softmax over TK per b -------------------------------------
__global__ void k_attn(float* __restrict__ out_attn) {
    __shared__ float red[32];
    int b = blockIdx.x, t = threadIdx.x;   // 1024 threads
    float s = g_scores[b * TKK + t];
    float m = s;
#pragma unroll
    for (int o = 16; o; o >>= 1) m = fmaxf(m, __shfl_xor_sync(0xffffffffu, m, o));
    if ((t & 31) == 0) red[t >> 5] = m;
    __syncthreads();
    if (t < 32) {
        float v = red[t];
#pragma unroll
        for (int o = 16; o; o >>= 1) v = fmaxf(v, __shfl_xor_sync(0xffffffffu, v, o));
        if (t == 0) red[0] = v;
    }
    __syncthreads();
    float mx = red[0];
    __syncthreads();
    float e = __expf(s - mx);
    float sm = e;
#pragma unroll
    for (int o = 16; o; o >>= 1) sm += __shfl_xor_sync(0xffffffffu, sm, o);
    if ((t & 31) == 0) red[t >> 5] = sm;
    __syncthreads();
    if (t < 32) {
        float v = red[t];
#pragma unroll
        for (int o = 16; o; o >>= 1) v += __shfl_xor_sync(0xffffffffu, v, o);
        if (t == 0) red[0] = v;
    }
    __syncthreads();
    out_attn[b * TKK + t] = e * (1.f / red[0]);
}

// ---------------- c_t partials ----------------------------------------------
__global__ void k_ct_part(const float* __restrict__ enc, const float* __restrict__ attn) {
    __shared__ float sa[64];
    int c = blockIdx.x, b = blockIdx.y, h = threadIdx.x;   // 512 threads
    if (h < 64) sa[h] = attn[b * TKK + c * 64 + h];
    __syncthreads();
    const float* e = enc + ((size_t)b * TKK + c * 64) * HH + h;
    float acc = 0.f;
#pragma unroll 8
    for (int t = 0; t < 64; t++) acc += sa[t] * e[(size_t)t * HH];
    g_cpart[((size_t)b * 16 + c) * HH + h] = acc;
}

__global__ void k_ct_fin(float* __restrict__ out_ct) {
    int b = blockIdx.x, h = threadIdx.x;   // 512
    float acc = 0.f;
#pragma unroll
    for (int c = 0; c < 16; c++) acc += g_cpart[((size_t)b * 16 + c) * HH + h];
    out_ct[b * HH + h] = acc;
    g_concatT[(HH + h) * BB + b] = acc;
}

// ---------------- logits via wmma, double buffered, 1 sync/iter -------------
#define LG_SMEM (33280 + 20480)
__global__ __launch_bounds__(256) void k_logits_mma(const float* __restrict__ W,
                                                    const float* __restrict__ bias) {
    extern __shared__ char smraw[];
    __nv_bfloat16* As2 = (__nv_bfloat16*)smraw;                // [32][520]
    __nv_bfloat16* Ws  = (__nv_bfloat16*)(smraw + 33280);      // [2][128][40]
    float* stage = (float*)(smraw + 33280);                    // [32][136]

    int tid = threadIdx.x, warp = tid >> 5;
    int n0 = blockIdx.x * 128;
    for (int idx = tid; idx < BB * HH; idx += 256) {
        int r = idx >> 9, k = idx & 511;
        As2[r * 520 + k] = __float2bfloat16(g_out1[idx]);
    }

    wmma::fragment<wmma::accumulator, 16, 16, 16, float> acc[2];
    wmma::fill_fragment(acc[0], 0.f);
    wmma::fill_fragment(acc[1], 0.f);

    int lrow = tid >> 3, lq = tid & 7;
    float4 wreg[4];
#pragma unroll
    for (int p = 0; p < 4; p++) {
        int n = n0 + p * 32 + lrow;
        wreg[p] = (n < VOCAB) ? *(const float4*)(W + (size_t)n * HH + lq * 4)
                              : make_float4(0.f, 0.f, 0.f, 0.f);
    }
    for (int it = 0; it < 16; it++) {
        int cur = it & 1;
        __nv_bfloat16* wd = Ws + cur * (128 * 40);
#pragma unroll
        for (int p = 0; p < 4; p++) {
            __nv_bfloat16* d = wd + (p * 32 + lrow) * 40 + lq * 4;
            *(__nv_bfloat162*)d       = __floats2bfloat162_rn(wreg[p].x, wreg[p].y);
            *(__nv_bfloat162*)(d + 2) = __floats2bfloat162_rn(wreg[p].z, wreg[p].w);
        }
        if (it < 15) {
#pragma unroll
            for (int p = 0; p < 4; p++) {
                int n = n0 + p * 32 + lrow;
                wreg[p] = (n < VOCAB)
                    ? *(const float4*)(W + (size_t)n * HH + (it + 1) * 32 + lq * 4)
                    : make_float4(0.f, 0.f, 0.f, 0.f);
            }
        }
        __syncthreads();    // publishes wd(it); cross-iter writes go to other buffer
#pragma unroll
        for (int kk = 0; kk < 32; kk += 16) {
            wmma::fragment<wmma::matrix_b, 16, 16, 16, __nv_bfloat16, wmma::col_major> bf;
            wmma::load_matrix_sync(bf, wd + (warp * 16) * 40 + kk, 40);
#pragma unroll
            for (int i = 0; i < 2; i++) {
                wmma::fragment<wmma::matrix_a, 16, 16, 16, __nv_bfloat16, wmma::row_major> af;
                wmma::load_matrix_sync(af, As2 + (i * 16) * 520 + it * 32 + kk, 520);
                wmma::mma_sync(acc[i], af, bf, acc[i]);
            }
        }
    }
    __syncthreads();
#pragma unroll
    for (int i = 0; i < 2; i++)
        wmma::store_matrix_sync(stage + (i * 16) * 136 + warp * 16, acc[i], 136,
                                wmma::mem_row_major);
    __syncthreads();
    for (int idx = tid; idx < 32 * 128; idx += 256) {
        int r = idx >> 7, c = idx & 127;
        int n = n0 + c;
        if (n < VOCAB)
            g_logits[(size_t)r * VOCAB + n] = stage[r * 136 + c] + bias[n];
    }
}

// ---------------- parallel vocab softmax ------------------------------------
#define SM_CH 3142
__global__ void k_smA() {
    __shared__ float red[32];
    int b = blockIdx.y, slab = blockIdx.x, tid = threadIdx.x;
    int start = slab * SM_CH;
    int end = min(start + SM_CH, VOCAB);
    const float* lg = g_logits + (size_t)b * VOCAB;

    float m = -1e30f;
    for (int n = start + tid; n < end; n += 256) m = fmaxf(m, lg[n]);
#pragma unroll
    for (int o = 16; o; o >>= 1) m = fmaxf(m, __shfl_xor_sync(0xffffffffu, m, o));
    if ((tid & 31) == 0) red[tid >> 5] = m;
    __syncthreads();
    if (tid < 32) {
        float v = (tid < 8) ? red[tid] : -1e30f;
#pragma unroll
        for (int o = 4; o; o >>= 1) v = fmaxf(v, __shfl_xor_sync(0xffffffffu, v, o));
        if (tid == 0) red[0] = v;
    }
    __syncthreads();
    float mx = red[0];
    __syncthreads();
    float s = 0.f;
    for (int n = start + tid; n < end; n += 256) s += __expf(lg[n] - mx);
#pragma unroll
    for (int o = 16; o; o >>= 1) s += __shfl_xor_sync(0xffffffffu, s, o);
    if ((tid & 31) == 0) red[tid >> 5] = s;
    __syncthreads();
    if (tid < 32) {
        float v = (tid < 8) ? red[tid] : 0.f;
#pragma unroll
        for (int o = 4; o; o >>= 1) v += __shfl_xor_sync(0xffffffffu, v, o);
        if (tid == 0) {
            g_smx[b * 16 + slab] = mx;
            g_sms[b * 16 + slab] = s = v;
        }
    }
}

__global__ void k_smB(float* __restrict__ out_fd) {
    int b = blockIdx.y, tid = threadIdx.x;
    float M = -1e30f;
#pragma unroll
    for (int i = 0; i < 16; i++) M = fmaxf(M, g_smx[b * 16 + i]);
    float S = 0.f;
#pragma unroll
    for (int i = 0; i < 16; i++) S += g_sms[b * 16 + i] * __expf(g_smx[b * 16 + i] - M);
    float inv = 1.f / S;
    const float* lg = g_logits + (size_t)b * VOCAB;
    float* dst = out_fd + (size_t)b * VOCAB;
    int base = blockIdx.x * 2048;
#pragma unroll
    for (int j = 0; j < 8; j++) {
        int n = base + j * 256 + tid;
        if (n < VOCAB) dst[n] = __expf(lg[n] - M) * inv;
    }
}

// ---------------- launcher ---------------------------------------------------
extern "C" void kernel_launch(void* const* d_in, const int* in_sizes, int n_in,
                              void* d_out, int out_size) {
    const int*   y      = (const int*)d_in[0];
    const float* s_t_1  = (const float*)d_in[2];
    const float* enc    = (const float*)d_in[3];
    const float* c_t_1  = (const float*)d_in[4];
    const float* cov    = (const float*)d_in[5];
    const float* emb    = (const float*)d_in[7];
    const float* xc_w   = (const float*)d_in[8];
    const float* xc_b   = (const float*)d_in[9];
    const float* Wh_w   = (const float*)d_in[10];
    const float* w_ih   = (const float*)d_in[11];
    const float* w_hh   = (const float*)d_in[12];
    const float* b_ih   = (const float*)d_in[13];
    const float* b_hh   = (const float*)d_in[14];
    const float* dp_w   = (const float*)d_in[15];
    const float* dp_b   = (const float*)d_in[16];
    const float* v_w    = (const float*)d_in[17];
    const float* out1_w = (const float*)d_in[18];
    const float* out1_b = (const float*)d_in[19];
    const float* out2_w = (const float*)d_in[20];
    const float* out2_b = (const float*)d_in[21];

    float* out      = (float*)d_out;
    float* out_fd   = out;
    float* out_st   = out_fd + (size_t)BB * VOCAB;
    float* out_ct   = out_st + BB * HH;
    float* out_attn = out_ct + BB * HH;
    float* out_cov  = out_attn + BB * TKK;

    float *p_concatT, *p_out1;
    cudaGetSymbolAddress((void**)&p_concatT, g_concatT);
    cudaGetSymbolAddress((void**)&p_out1,    g_out1);

    cudaFuncSetAttribute(k_fat3, cudaFuncAttributeMaxDynamicSharedMemorySize, F3_SMEM);
    cudaFuncSetAttribute(k_logits_mma, cudaFuncAttributeMaxDynamicSharedMemorySize, LG_SMEM);

    k_convert_wh<<<512, 256>>>(Wh_w);                                      // 0
    k_convert_enc<<<8192, 256>>>(enc);                                     // 1
    k_frontend<<<FE_BLOCKS, FE_THREADS>>>(y, c_t_1, s_t_1, emb,
                                          xc_w, xc_b, w_ih, b_ih, w_hh, b_hh,
                                          dp_w, dp_b, out1_b, out_st);     // 2
    k_fat3<<<dim3(M_ENC / 64, 2), 256, F3_SMEM>>>(v_w);                    // 3 <- profiled
    k_attn<<<BB, 1024>>>(out_attn);                                        // 4
    k_ct_part<<<dim3(16, BB), 512>>>(enc, out_attn);                       // 5
    k_ct_fin<<<BB, 512>>>(out_ct);                                         // 6
    k_bsplit<<<dim3(HH / 8, 8), 256>>>(nullptr, p_out1, p_concatT, out1_w, HH, 2 * HH);
    k_logits_mma<<<(VOCAB + 127) / 128, 256, LG_SMEM>>>(out2_w, out2_b);
    k_smA<<<dim3(16, BB), 256>>>();
    k_smB<<<dim3(25, BB), 256>>>(out_fd);
    cudaMemcpyAsync(out_cov, cov, (size_t)BB * TKK * sizeof(float),
                    cudaMemcpyDeviceToDevice, 0);
}